// round 11
// baseline (speedup 1.0000x reference)
#include <cuda_runtime.h>
#include <cuda_bf16.h>
#include <math.h>

#define NMAX 20000
#define EMAX 320000
#define ETMAX (NMAX + EMAX)
#define DIM 512
#define H1 8
#define C1 64

// ---------------- scratch (static device memory; no allocations) -------------
__device__ float g_bufA[NMAX * DIM];   // GEMM fp32 outputs
__device__ float g_bufC[NMAX * DIM];   // fc output (post-relu) for BN
__device__ float g_als[NMAX * H1];
__device__ float g_ald[NMAX * H1];
__device__ float g_sum[DIM];
__device__ float g_sumsq[DIM];
__device__ int g_cnt[NMAX];
__device__ int g_rowptr[NMAX + 1];
__device__ int g_cursor[NMAX];
__device__ int g_srcs[ETMAX];
// packed bf16 hi/lo operands
__device__ unsigned g_actH[NMAX * 256];
__device__ unsigned g_actL[NMAX * 256];
__device__ unsigned g_WH[425984];
__device__ unsigned g_WL[425984];

// ================= CSR build ==================================================
__global__ void csr_zero(int n) {
    int i = blockIdx.x * blockDim.x + threadIdx.x;
    if (i < n) g_cnt[i] = 0;
}

__global__ void csr_hist(const int* __restrict__ ei, int E, int n) {
    int e = blockIdx.x * blockDim.x + threadIdx.x;
    if (e >= E + n) return;
    int dst = (e < E) ? ei[E + e] : e - E;
    atomicAdd(&g_cnt[dst], 1);
}

__global__ void csr_scan(int n, int Et) {
    __shared__ int part[1024];
    int tid = threadIdx.x;
    int chunk = (n + 1023) / 1024;
    int lo = tid * chunk;
    int hi = lo + chunk; if (hi > n) hi = n; if (lo > n) lo = n;
    int s = 0;
    for (int i = lo; i < hi; i++) s += g_cnt[i];
    part[tid] = s;
    __syncthreads();
    for (int off = 1; off < 1024; off <<= 1) {
        int v = (tid >= off) ? part[tid - off] : 0;
        __syncthreads();
        part[tid] += v;
        __syncthreads();
    }
    int run = (tid == 0) ? 0 : part[tid - 1];
    for (int i = lo; i < hi; i++) {
        g_rowptr[i] = run;
        g_cursor[i] = run;
        run += g_cnt[i];
    }
    if (tid == 1023) g_rowptr[n] = Et;
}

__global__ void csr_scatter(const int* __restrict__ ei, int E, int n) {
    int e = blockIdx.x * blockDim.x + threadIdx.x;
    if (e >= E + n) return;
    int src, dst;
    if (e < E) { src = ei[e]; dst = ei[E + e]; }
    else       { src = dst = e - E; }
    int pos = atomicAdd(&g_cursor[dst], 1);
    g_srcs[pos] = src;
}

// ================= misc ========================================================
__global__ void zero2(float* __restrict__ a, float* __restrict__ b, int n) {
    int i = blockIdx.x * blockDim.x + threadIdx.x;
    if (i < n) { a[i] = 0.f; b[i] = 0.f; }
}

// ================= bf16 split/pack helpers ====================================
__device__ __forceinline__ void split_pack2(float v0, float v1,
                                            unsigned& hw, unsigned& lw) {
    __nv_bfloat16 h0 = __float2bfloat16_rn(v0);
    __nv_bfloat16 h1 = __float2bfloat16_rn(v1);
    __nv_bfloat16 l0 = __float2bfloat16_rn(v0 - __bfloat162float(h0));
    __nv_bfloat16 l1 = __float2bfloat16_rn(v1 - __bfloat162float(h1));
    __nv_bfloat162 hp = __halves2bfloat162(h0, h1);
    __nv_bfloat162 lp = __halves2bfloat162(l0, l1);
    hw = *(unsigned*)&hp;
    lw = *(unsigned*)&lp;
}

// one launch packs all 4 weight matrices + the input activations
__global__ void pack_all(const float* __restrict__ W1, const float* __restrict__ fc1w,
                         const float* __restrict__ W2, const float* __restrict__ fc2w,
                         const float* __restrict__ x,
                         unsigned* __restrict__ wH, unsigned* __restrict__ wL,
                         unsigned* __restrict__ aH, unsigned* __restrict__ aL, int n)
{
    int t = blockIdx.x * blockDim.x + threadIdx.x;
    if (t < 106496) {
        const float* W; int off; int u = t;
        if (t < 8192)       { W = W1;   off = 0; }
        else if (t < 40960) { W = fc1w; off = 32768;  u = t - 8192; }
        else if (t < 73728) { W = W2;   off = 163840; u = t - 40960; }
        else                { W = fc2w; off = 294912; u = t - 73728; }
        int k2 = u >> 7;          // N/4 = 128 groups per k2 row
        int n4 = u & 127;
        const float* p0 = W + (size_t)(2 * k2) * DIM + n4 * 4;
        const float* p1 = p0 + DIM;
        float4 a = *(const float4*)p0;
        float4 b = *(const float4*)p1;
        uint4 h, l;
        split_pack2(a.x, b.x, h.x, l.x);
        split_pack2(a.y, b.y, h.y, l.y);
        split_pack2(a.z, b.z, h.z, l.z);
        split_pack2(a.w, b.w, h.w, l.w);
        *(uint4*)(wH + off + (size_t)u * 4) = h;
        *(uint4*)(wL + off + (size_t)u * 4) = l;
    } else {
        int u = t - 106496;
        if (u >= n * 16) return;
        const float* p = x + (size_t)u * 8;
        float4 v0 = *(const float4*)p;
        float4 v1 = *(const float4*)(p + 4);
        uint4 h, l;
        split_pack2(v0.x, v0.y, h.x, l.x);
        split_pack2(v0.z, v0.w, h.y, l.y);
        split_pack2(v1.x, v1.y, h.z, l.z);
        split_pack2(v1.z, v1.w, h.w, l.w);
        *(uint4*)(aH + (size_t)u * 4) = h;
        *(uint4*)(aL + (size_t)u * 4) = l;
    }
}

// ================= BF16x3 GEMM, 3-stage cp.async, fused epilogues =============
__device__ __forceinline__ void mma_bf16(float* d, const unsigned* a, const unsigned* b) {
    asm volatile(
        "mma.sync.aligned.m16n8k16.row.col.f32.bf16.bf16.f32 "
        "{%0,%1,%2,%3}, {%4,%5,%6,%7}, {%8,%9}, {%0,%1,%2,%3};"
        : "+f"(d[0]), "+f"(d[1]), "+f"(d[2]), "+f"(d[3])
        : "r"(a[0]), "r"(a[1]), "r"(a[2]), "r"(a[3]), "r"(b[0]), "r"(b[1]));
}

__device__ __forceinline__ void cp16(unsigned smem_addr, const void* gptr, int src_sz) {
    asm volatile("cp.async.ca.shared.global [%0], [%1], 16, %2;"
                 :: "r"(smem_addr), "l"(gptr), "r"(src_sz));
}

#define SA 12
#define SB 136
#define NSTG 3
// dyn smem words: 2*NSTG*128*SA (A H+L) + 2*NSTG*8*SB (B H+L) + 768 epilogue
#define GEMM_SMEM_WORDS (2 * NSTG * 128 * SA + 2 * NSTG * 8 * SB + 768)
#define GEMM_SMEM_BYTES (GEMM_SMEM_WORDS * 4)

__global__ __launch_bounds__(256) void gemm_pk(
    const unsigned* __restrict__ AH, const unsigned* __restrict__ AL, int lda2,
    const unsigned* __restrict__ BH, const unsigned* __restrict__ BL,
    const float* __restrict__ bias, float* __restrict__ C,
    int M, int N, int K2, int has_bias, int do_relu,
    int attn_mode, const float* __restrict__ a_s, const float* __restrict__ a_d,
    float* __restrict__ als, float* __restrict__ ald, int do_stats)
{
    extern __shared__ unsigned dsm[];
    unsigned* bAH = dsm;                              // NSTG*128*SA
    unsigned* bAL = bAH + NSTG * 128 * SA;
    unsigned* bBH = bAL + NSTG * 128 * SA;            // NSTG*8*SB
    unsigned* bBL = bBH + NSTG * 8 * SB;
    float* sm_ps = (float*)(bBL + NSTG * 8 * SB);     // 128*2
    float* sm_pd = sm_ps + 256;
    float* sm_cs = sm_pd + 256;                       // 128
    float* sm_cq = sm_cs + 128;                       // 128

    int tid  = threadIdx.x;
    int warp = tid >> 5;
    int lane = tid & 31;
    int grp  = lane >> 2;
    int l4   = lane & 3;

    int m0 = blockIdx.y * 128;
    int n0 = blockIdx.x * 128;
    int wm = (warp >> 2) * 64;
    int wn = (warp & 3) * 32;

    float acc[4][4][4];
#pragma unroll
    for (int mi = 0; mi < 4; mi++)
#pragma unroll
        for (int ni = 0; ni < 4; ni++)
#pragma unroll
            for (int r = 0; r < 4; r++) acc[mi][ni][r] = 0.f;

    int a_row = tid >> 1;
    int a_ch  = (tid & 1) * 4;
    int b_row = tid >> 5;
    int b_ch  = (tid & 31) * 4;
    int a_ok  = (m0 + a_row < M) ? 16 : 0;
    const unsigned* Arow_h = AH + (size_t)(m0 + a_row) * lda2 + a_ch;
    const unsigned* Arow_l = AL + (size_t)(m0 + a_row) * lda2 + a_ch;
    const unsigned* Brow_h = BH + (size_t)b_row * N + n0 + b_ch;
    const unsigned* Brow_l = BL + (size_t)b_row * N + n0 + b_ch;

    unsigned sbase = (unsigned)__cvta_generic_to_shared(dsm);
    const unsigned stA = 128 * SA * 4;
    const unsigned stB = 8 * SB * 4;
    const unsigned oAH = 0;
    const unsigned oAL = NSTG * stA;
    const unsigned oBH = 2 * NSTG * stA;
    const unsigned oBL = oBH + NSTG * stB;
    unsigned aoff = a_row * SA * 4 + a_ch * 4;
    unsigned boff = b_row * SB * 4 + b_ch * 4;

#define GISSUE(tt) do {                                                       \
        int _s = (tt) % 3;                                                    \
        int _k = (tt) * 8;                                                    \
        cp16(sbase + oAH + _s * stA + aoff, Arow_h + _k, a_ok);               \
        cp16(sbase + oAL + _s * stA + aoff, Arow_l + _k, a_ok);               \
        cp16(sbase + oBH + _s * stB + boff, Brow_h + (size_t)_k * N, 16);     \
        cp16(sbase + oBL + _s * stB + boff, Brow_l + (size_t)_k * N, 16);     \
        asm volatile("cp.async.commit_group;");                               \
    } while (0)

    int nt = K2 >> 3;

    GISSUE(0);
    GISSUE(1);

    for (int t = 0; t < nt; t++) {
        if (t + 1 < nt) asm volatile("cp.async.wait_group 1;");
        else            asm volatile("cp.async.wait_group 0;");
        __syncthreads();
        if (t + 2 < nt) GISSUE(t + 2);   // targets stage (t+2)%3 == (t-1)%3: sealed by barrier

        int s = t % 3;
        const unsigned* pAH = bAH + s * 128 * SA;
        const unsigned* pAL = bAL + s * 128 * SA;
        const unsigned* pBH = bBH + s * 8 * SB;
        const unsigned* pBL = bBL + s * 8 * SB;

        unsigned ah[4][4], al[4][4], bh[4][2], bl[4][2];
#pragma unroll
        for (int mi = 0; mi < 4; mi++) {
            int rm = wm + mi * 16 + grp;
            ah[mi][0] = pAH[rm * SA + l4];
            ah[mi][1] = pAH[(rm + 8) * SA + l4];
            ah[mi][2] = pAH[rm * SA + l4 + 4];
            ah[mi][3] = pAH[(rm + 8) * SA + l4 + 4];
            al[mi][0] = pAL[rm * SA + l4];
            al[mi][1] = pAL[(rm + 8) * SA + l4];
            al[mi][2] = pAL[rm * SA + l4 + 4];
            al[mi][3] = pAL[(rm + 8) * SA + l4 + 4];
        }
#pragma unroll
        for (int ni = 0; ni < 4; ni++) {
            int nn = wn + ni * 8 + grp;
            bh[ni][0] = pBH[l4 * SB + nn];
            bh[ni][1] = pBH[(l4 + 4) * SB + nn];
            bl[ni][0] = pBL[l4 * SB + nn];
            bl[ni][1] = pBL[(l4 + 4) * SB + nn];
        }
#pragma unroll
        for (int mi = 0; mi < 4; mi++)
#pragma unroll
            for (int ni = 0; ni < 4; ni++) {
                mma_bf16(acc[mi][ni], ah[mi], bh[ni]);
                mma_bf16(acc[mi][ni], ah[mi], bl[ni]);
                mma_bf16(acc[mi][ni], al[mi], bh[ni]);
            }
    }

    // ---- fused epilogue ----
    int fused = (attn_mode != 0) || do_stats;
    if (fused) {
        __syncthreads();
        if (tid < 128) {
            sm_ps[tid * 2] = 0.f; sm_ps[tid * 2 + 1] = 0.f;
            sm_pd[tid * 2] = 0.f; sm_pd[tid * 2 + 1] = 0.f;
            sm_cs[tid] = 0.f;     sm_cq[tid] = 0.f;
        }
        __syncthreads();
    }

    float as_c[8], ad_c[8];
    if (attn_mode) {
#pragma unroll
        for (int ni = 0; ni < 4; ni++) {
            int gc = n0 + wn + ni * 8 + l4 * 2;
            as_c[ni * 2] = a_s[gc];     as_c[ni * 2 + 1] = a_s[gc + 1];
            ad_c[ni * 2] = a_d[gc];     ad_c[ni * 2 + 1] = a_d[gc + 1];
        }
    }
    float ps[8], pd[8], cs[8], cq[8];
#pragma unroll
    for (int q = 0; q < 8; q++) { ps[q] = pd[q] = cs[q] = cq[q] = 0.f; }

#pragma unroll
    for (int mi = 0; mi < 4; mi++) {
        int r0 = m0 + wm + mi * 16 + grp;
        int r1 = r0 + 8;
        bool ok0 = (r0 < M), ok1 = (r1 < M);
#pragma unroll
        for (int ni = 0; ni < 4; ni++) {
            int c = n0 + wn + ni * 8 + l4 * 2;
            float2 v0 = make_float2(acc[mi][ni][0], acc[mi][ni][1]);
            float2 v1 = make_float2(acc[mi][ni][2], acc[mi][ni][3]);
            if (has_bias) {
                float2 bv = *(const float2*)(bias + c);
                v0.x += bv.x; v0.y += bv.y;
                v1.x += bv.x; v1.y += bv.y;
            }
            if (do_relu) {
                v0.x = fmaxf(v0.x, 0.f); v0.y = fmaxf(v0.y, 0.f);
                v1.x = fmaxf(v1.x, 0.f); v1.y = fmaxf(v1.y, 0.f);
            }
            if (attn_mode) {
                if (ok0) {
                    ps[mi * 2]     += v0.x * as_c[ni * 2] + v0.y * as_c[ni * 2 + 1];
                    pd[mi * 2]     += v0.x * ad_c[ni * 2] + v0.y * ad_c[ni * 2 + 1];
                }
                if (ok1) {
                    ps[mi * 2 + 1] += v1.x * as_c[ni * 2] + v1.y * as_c[ni * 2 + 1];
                    pd[mi * 2 + 1] += v1.x * ad_c[ni * 2] + v1.y * ad_c[ni * 2 + 1];
                }
            }
            if (do_stats) {
                float x0 = ok0 ? v0.x : 0.f, y0 = ok0 ? v0.y : 0.f;
                float x1 = ok1 ? v1.x : 0.f, y1 = ok1 ? v1.y : 0.f;
                cs[ni * 2]     += x0 + x1;
                cq[ni * 2]     += x0 * x0 + x1 * x1;
                cs[ni * 2 + 1] += y0 + y1;
                cq[ni * 2 + 1] += y0 * y0 + y1 * y1;
            }
            if (ok0) *(float2*)(C + (size_t)r0 * N + c) = v0;
            if (ok1) *(float2*)(C + (size_t)r1 * N + c) = v1;
        }
    }

    if (attn_mode) {
        int hsel = wn >> 6;
#pragma unroll
        for (int q = 0; q < 8; q++) {
            float vs = ps[q], vd = pd[q];
            vs += __shfl_xor_sync(0xffffffffu, vs, 1);
            vs += __shfl_xor_sync(0xffffffffu, vs, 2);
            vd += __shfl_xor_sync(0xffffffffu, vd, 1);
            vd += __shfl_xor_sync(0xffffffffu, vd, 2);
            if (l4 == 0) {
                int rt = wm + (q >> 1) * 16 + grp + (q & 1) * 8;
                atomicAdd(&sm_ps[rt * 2 + hsel], vs);
                atomicAdd(&sm_pd[rt * 2 + hsel], vd);
            }
        }
    }
    if (do_stats) {
#pragma unroll
        for (int q = 0; q < 8; q++) {
            float s = cs[q], sq = cq[q];
            s  += __shfl_xor_sync(0xffffffffu, s, 4);
            s  += __shfl_xor_sync(0xffffffffu, s, 8);
            s  += __shfl_xor_sync(0xffffffffu, s, 16);
            sq += __shfl_xor_sync(0xffffffffu, sq, 4);
            sq += __shfl_xor_sync(0xffffffffu, sq, 8);
            sq += __shfl_xor_sync(0xffffffffu, sq, 16);
            if (grp == 0) {
                int ct = wn + (q >> 1) * 8 + l4 * 2 + (q & 1);
                atomicAdd(&sm_cs[ct], s);
                atomicAdd(&sm_cq[ct], sq);
            }
        }
    }
    if (fused) {
        __syncthreads();
        if (tid < 128) {
            int gr = m0 + tid;
            if (attn_mode == 8 && gr < M) {
                int h0 = n0 >> 6;
                als[gr * 8 + h0]     = sm_ps[tid * 2];
                als[gr * 8 + h0 + 1] = sm_ps[tid * 2 + 1];
                ald[gr * 8 + h0]     = sm_pd[tid * 2];
                ald[gr * 8 + h0 + 1] = sm_pd[tid * 2 + 1];
            } else if (attn_mode == 1 && gr < M) {
                atomicAdd(&als[gr], sm_ps[tid * 2] + sm_ps[tid * 2 + 1]);
                atomicAdd(&ald[gr], sm_pd[tid * 2] + sm_pd[tid * 2 + 1]);
            }
            if (do_stats) {
                atomicAdd(&g_sum[n0 + tid], sm_cs[tid]);
                atomicAdd(&g_sumsq[n0 + tid], sm_cq[tid]);
            }
        }
    }
}

// ================= fused GAT softmax+aggregate (CSR, smem-staged) ==============
#define CHUNK 128

__global__ __launch_bounds__(256) void gat_agg8(
    const float* __restrict__ h, const float* __restrict__ als,
    const float* __restrict__ ald, const float* __restrict__ bias,
    unsigned* __restrict__ outH, unsigned* __restrict__ outL)
{
    __shared__ int sh_src[CHUNK];
    __shared__ float sh_w[CHUNK][8];
    __shared__ float sh_mx[8], sh_inv[8], sh_ald[8];

    int dst = blockIdx.x;
    int tid = threadIdx.x;
    int warp = tid >> 5;
    int lane = tid & 31;
    int r0 = g_rowptr[dst], r1 = g_rowptr[dst + 1];

    {
        float aldv = ald[dst * 8 + warp];
        if (lane == 0) sh_ald[warp] = aldv;
        float mx = -1e30f;
        for (int i = r0 + lane; i < r1; i += 32) {
            int s = g_srcs[i];
            float ev = als[s * 8 + warp] + aldv;
            ev = (ev > 0.f) ? ev : 0.2f * ev;
            mx = fmaxf(mx, ev);
        }
#pragma unroll
        for (int o = 16; o; o >>= 1) mx = fmaxf(mx, __shfl_xor_sync(0xffffffffu, mx, o));
        float sum = 0.f;
        for (int i = r0 + lane; i < r1; i += 32) {
            int s = g_srcs[i];
            float ev = als[s * 8 + warp] + aldv;
            ev = (ev > 0.f) ? ev : 0.2f * ev;
            sum += __expf(ev - mx);
        }
#pragma unroll
        for (int o = 16; o; o >>= 1) sum += __shfl_xor_sync(0xffffffffu, sum, o);
        if (lane == 0) { sh_mx[warp] = mx; sh_inv[warp] = 1.f / sum; }
    }

    int c = tid * 2;
    int hh = warp;
    float2 acc = make_float2(0.f, 0.f);

    for (int base = r0; base < r1; base += CHUNK) {
        int cnt = min(CHUNK, r1 - base);
        __syncthreads();
        if (tid < cnt) sh_src[tid] = g_srcs[base + tid];
        __syncthreads();
        for (int t = tid; t < cnt * 8; t += 256) {
            int i = t >> 3, hw = t & 7;
            int s = sh_src[i];
            float ev = als[s * 8 + hw] + sh_ald[hw];
            ev = (ev > 0.f) ? ev : 0.2f * ev;
            sh_w[i][hw] = __expf(ev - sh_mx[hw]) * sh_inv[hw];
        }
        __syncthreads();
        int i = 0;
        for (; i + 4 <= cnt; i += 4) {
            int s0 = sh_src[i], s1 = sh_src[i + 1], s2 = sh_src[i + 2], s3 = sh_src[i + 3];
            float w0 = sh_w[i][hh], w1 = sh_w[i + 1][hh],
                  w2 = sh_w[i + 2][hh], w3 = sh_w[i + 3][hh];
            float2 v0 = *(const float2*)(h + (size_t)s0 * DIM + c);
            float2 v1 = *(const float2*)(h + (size_t)s1 * DIM + c);
            float2 v2 = *(const float2*)(h + (size_t)s2 * DIM + c);
            float2 v3 = *(const float2*)(h + (size_t)s3 * DIM + c);
            acc.x = fmaf(w0, v0.x, acc.x); acc.y = fmaf(w0, v0.y, acc.y);
            acc.x = fmaf(w1, v1.x, acc.x); acc.y = fmaf(w1, v1.y, acc.y);
            acc.x = fmaf(w2, v2.x, acc.x); acc.y = fmaf(w2, v2.y, acc.y);
            acc.x = fmaf(w3, v3.x, acc.x); acc.y = fmaf(w3, v3.y, acc.y);
        }
        for (; i < cnt; i++) {
            int s = sh_src[i];
            float w = sh_w[i][hh];
            float2 v = *(const float2*)(h + (size_t)s * DIM + c);
            acc.x = fmaf(w, v.x, acc.x); acc.y = fmaf(w, v.y, acc.y);
        }
    }

    float2 bv = *(const float2*)(bias + c);
    acc.x += bv.x; acc.y += bv.y;
    unsigned hw, lw;
    split_pack2(acc.x, acc.y, hw, lw);
    int wi = dst * 256 + tid;
    outH[wi] = hw; outL[wi] = lw;
}

__global__ __launch_bounds__(256) void gat_agg1(
    const float* __restrict__ h, const float* __restrict__ als,
    const float* __restrict__ ald, const float* __restrict__ bias,
    unsigned* __restrict__ outH, unsigned* __restrict__ outL)
{
    __shared__ int sh_src[CHUNK];
    __shared__ float sh_w[CHUNK];
    __shared__ float sh_mx, sh_inv;

    int dst = blockIdx.x;
    int tid = threadIdx.x;
    int r0 = g_rowptr[dst], r1 = g_rowptr[dst + 1];
    float aldv = ald[dst];

    if (tid < 32) {
        float mx = -1e30f;
        for (int i = r0 + tid; i < r1; i += 32) {
            int s = g_srcs[i];
            float ev = als[s] + aldv;
            ev = (ev > 0.f) ? ev : 0.2f * ev;
            mx = fmaxf(mx, ev);
        }
#pragma unroll
        for (int o = 16; o; o >>= 1) mx = fmaxf(mx, __shfl_xor_sync(0xffffffffu, mx, o));
        float sum = 0.f;
        for (int i = r0 + tid; i < r1; i += 32) {
            int s = g_srcs[i];
            float ev = als[s] + aldv;
            ev = (ev > 0.f) ? ev : 0.2f * ev;
            sum += __expf(ev - mx);
        }
#pragma unroll
        for (int o = 16; o; o >>= 1) sum += __shfl_xor_sync(0xffffffffu, sum, o);
        if (tid == 0) { sh_mx = mx; sh_inv = 1.f / sum; }
    }

    int c = tid * 2;
    float2 acc = make_float2(0.f, 0.f);

    for (int base = r0; base < r1; base += CHUNK) {
        int cnt = min(CHUNK, r1 - base);
        __syncthreads();
        if (tid < cnt) sh_src[tid] = g_srcs[base + tid];
        __syncthreads();
        for (int t = tid; t < cnt; t += 256) {
            int s = sh_src[t];
            float ev = als[s] + aldv;
            ev = (ev > 0.f) ? ev : 0.2f * ev;
            sh_w[t] = __expf(ev - sh_mx) * sh_inv;
        }
        __syncthreads();
        int i = 0;
        for (; i + 4 <= cnt; i += 4) {
            int s0 = sh_src[i], s1 = sh_src[i + 1], s2 = sh_src[i + 2], s3 = sh_src[i + 3];
            float w0 = sh_w[i], w1 = sh_w[i + 1], w2 = sh_w[i + 2], w3 = sh_w[i + 3];
            float2 v0 = *(const float2*)(h + (size_t)s0 * DIM + c);
            float2 v1 = *(const float2*)(h + (size_t)s1 * DIM + c);
            float2 v2 = *(const float2*)(h + (size_t)s2 * DIM + c);
            float2 v3 = *(const float2*)(h + (size_t)s3 * DIM + c);
            acc.x = fmaf(w0, v0.x, acc.x); acc.y = fmaf(w0, v0.y, acc.y);
            acc.x = fmaf(w1, v1.x, acc.x); acc.y = fmaf(w1, v1.y, acc.y);
            acc.x = fmaf(w2, v2.x, acc.x); acc.y = fmaf(w2, v2.y, acc.y);
            acc.x = fmaf(w3, v3.x, acc.x); acc.y = fmaf(w3, v3.y, acc.y);
        }
        for (; i < cnt; i++) {
            int s = sh_src[i];
            float w = sh_w[i];
            float2 v = *(const float2*)(h + (size_t)s * DIM + c);
            acc.x = fmaf(w, v.x, acc.x); acc.y = fmaf(w, v.y, acc.y);
        }
    }

    float2 bv = *(const float2*)(bias + c);
    acc.x += bv.x; acc.y += bv.y;
    unsigned hw, lw;
    split_pack2(acc.x, acc.y, hw, lw);
    int wi = dst * 256 + tid;
    outH[wi] = hw; outL[wi] = lw;
}

// ================= BN apply (+ optional fused final linear) ===================
__global__ __launch_bounds__(256) void bn_apply(
    const float* __restrict__ x,
    const float* __restrict__ gamma, const float* __restrict__ beta,
    unsigned* __restrict__ outH, unsigned* __restrict__ outL,
    const float* __restrict__ linw, const float* __restrict__ linb,
    float* __restrict__ out, int n, int mode)
{
    __shared__ float rs[8][2];
    int row = blockIdx.x;
    int c2 = threadIdx.x;
    int col = c2 * 2;
    float inv_n = 1.f / (float)n;
    float mu0 = g_sum[col] * inv_n;
    float mu1 = g_sum[col + 1] * inv_n;
    float var0 = g_sumsq[col] * inv_n - mu0 * mu0;
    float var1 = g_sumsq[col + 1] * inv_n - mu1 * mu1;
    float2 xv = *(const float2*)(x + (size_t)row * DIM + col);
    float y0 = fmaf(gamma[col] * (xv.x - mu0), rsqrtf(var0 + 1e-5f), beta[col]);
    float y1 = fmaf(gamma[col + 1] * (xv.y - mu1), rsqrtf(var1 + 1e-5f), beta[col + 1]);

    if (mode == 0) {
        unsigned hw, lw;
        split_pack2(y0, y1, hw, lw);
        int wi = row * 256 + c2;
        outH[wi] = hw; outL[wi] = lw;
    } else {
        float p0 = y0 * linw[col * 2]     + y1 * linw[col * 2 + 2];
        float p1 = y0 * linw[col * 2 + 1] + y1 * linw[col * 2 + 3];
#pragma unroll
        for (int o = 16; o; o >>= 1) {
            p0 += __shfl_down_sync(0xffffffffu, p0, o);
            p1 += __shfl_down_sync(0xffffffffu, p1, o);
        }
        int warp = c2 >> 5, lane = c2 & 31;
        if (lane == 0) { rs[warp][0] = p0; rs[warp][1] = p1; }
        __syncthreads();
        if (c2 == 0) {
            float s0 = 0.f, s1 = 0.f;
#pragma unroll
            for (int w = 0; w < 8; w++) { s0 += rs[w][0]; s1 += rs[w][1]; }
            out[row * 2 + 0] = fmaxf(s0 + linb[0], 0.f);
            out[row * 2 + 1] = fmaxf(s1 + linb[1], 0.f);
        }
    }
}

// ------------------------------------------------------------------------------
extern "C" void kernel_launch(void* const* d_in, const int* in_sizes, int n_in,
                              void* d_out, int out_size)
{
    const float* x    = (const float*)d_in[0];
    const int*   ei   = (const int*)d_in[1];
    const float* W1   = (const float*)d_in[2];
    const float* a1s  = (const float*)d_in[3];
    const float* a1d  = (const float*)d_in[4];
    const float* b1   = (const float*)d_in[5];
    const float* W2   = (const float*)d_in[6];
    const float* a2s  = (const float*)d_in[7];
    const float* a2d  = (const float*)d_in[8];
    const float* b2   = (const float*)d_in[9];
    const float* fc1w = (const float*)d_in[10];
    const float* fc1b = (const float*)d_in[11];
    const float* g1   = (const float*)d_in[12];
    const float* be1  = (const float*)d_in[13];
    const float* fc2w = (const float*)d_in[14];
    const float* fc2b = (const float*)d_in[15];
    const float* g2   = (const float*)d_in[16];
    const float* be2  = (const float*)d_in[17];
    const float* linw = (const float*)d_in[18];
    const float* linb = (const float*)d_in[19];
    float* out = (float*)d_out;

    int n = out_size / 2;        // 20000
    int E = in_sizes[1] / 2;     // 320000
    int Et = E + n;

    float *A, *C, *als, *ald, *sum, *sumsq;
    unsigned *aH, *aL, *wH, *wL;
    cudaGetSymbolAddress((void**)&A,     g_bufA);
    cudaGetSymbolAddress((void**)&C,     g_bufC);
    cudaGetSymbolAddress((void**)&als,   g_als);
    cudaGetSymbolAddress((void**)&ald,   g_ald);
    cudaGetSymbolAddress((void**)&sum,   g_sum);
    cudaGetSymbolAddress((void**)&sumsq, g_sumsq);
    cudaGetSymbolAddress((void**)&aH,    g_actH);
    cudaGetSymbolAddress((void**)&aL,    g_actL);
    cudaGetSymbolAddress((void**)&wH,    g_WH);
    cudaGetSymbolAddress((void**)&wL,    g_WL);

    const int OW1 = 0, OF1 = 32768, OW2 = 163840, OF2 = 294912;

    static int smem_set = 0;
    if (!smem_set) {
        cudaFuncSetAttribute(gemm_pk, cudaFuncAttributeMaxDynamicSharedMemorySize,
                             GEMM_SMEM_BYTES);
        smem_set = 1;
    }

    dim3 gemm_grid(DIM / 128, (n + 127) / 128);

    // ---------------- CSR build ----------------
    csr_zero<<<(n + 255) / 256, 256>>>(n);
    csr_hist<<<(Et + 255) / 256, 256>>>(ei, E, n);
    csr_scan<<<1, 1024>>>(n, Et);
    csr_scatter<<<(Et + 255) / 256, 256>>>(ei, E, n);

    // ---------------- pack weights + input (single launch) ----------------
    pack_all<<<(106496 + n * 16 + 255) / 256, 256>>>(W1, fc1w, W2, fc2w, x,
                                                     wH, wL, aH, aL, n);

    // ---------------- layer 1: GATConv(128 -> 8x64), attn fused ----------------
    gemm_pk<<<gemm_grid, 256, GEMM_SMEM_BYTES>>>(
        aH, aL, 64, wH + OW1, wL + OW1, nullptr, A,
        n, DIM, 64, 0, 0, 8, a1s, a1d, als, ald, 0);
    gat_agg8<<<n, 256>>>(A, als, ald, b1, aH, aL);

    // ---------------- fc1 + relu + BN (stats fused) ----------------
    zero2<<<2, 256>>>(sum, sumsq, DIM);
    gemm_pk<<<gemm_grid, 256, GEMM_SMEM_BYTES>>>(
        aH, aL, 256, wH + OF1, wL + OF1, fc1b, C,
        n, DIM, 256, 1, 1, 0, nullptr, nullptr, nullptr, nullptr, 1);
    bn_apply<<<n, 256>>>(C, g1, be1, aH, aL, nullptr, nullptr, nullptr, n, 0);

    // ---------------- layer 2: GATConv(512 -> 1x512), attn fused (atomic) ------
    zero2<<<(n + 255) / 256, 256>>>(als, ald, n);
    gemm_pk<<<gemm_grid, 256, GEMM_SMEM_BYTES>>>(
        aH, aL, 256, wH + OW2, wL + OW2, nullptr, A,
        n, DIM, 256, 0, 0, 1, a2s, a2d, als, ald, 0);
    gat_agg1<<<n, 256>>>(A, als, ald, b2, aH, aL);

    // ---------------- fc2 + relu + BN (stats fused) + final linear -------------
    zero2<<<2, 256>>>(sum, sumsq, DIM);
    gemm_pk<<<gemm_grid, 256, GEMM_SMEM_BYTES>>>(
        aH, aL, 256, wH + OF2, wL + OF2, fc2b, C,
        n, DIM, 256, 1, 1, 0, nullptr, nullptr, nullptr, nullptr, 1);
    bn_apply<<<n, 256>>>(C, g2, be2, nullptr, nullptr, linw, linb, out, n, 1);
}

// round 12
// speedup vs baseline: 1.0131x; 1.0131x over previous
#include <cuda_runtime.h>
#include <cuda_bf16.h>
#include <math.h>

#define NMAX 20000
#define EMAX 320000
#define ETMAX (NMAX + EMAX)
#define DIM 512
#define H1 8
#define C1 64

// ---------------- scratch (static device memory; no allocations) -------------
__device__ float g_bufA[NMAX * DIM];   // GEMM fp32 outputs
__device__ float g_bufC[NMAX * DIM];   // fc output (post-relu) for BN
__device__ float g_als[NMAX * H1];
__device__ float g_ald[NMAX * H1];
__device__ float g_sum[DIM];
__device__ float g_sumsq[DIM];
__device__ int g_cnt[NMAX];
__device__ int g_rowptr[NMAX + 1];
__device__ int g_cursor[NMAX];
__device__ int g_srcs[ETMAX];
// packed bf16 hi/lo operands
__device__ unsigned g_actH[NMAX * 256];
__device__ unsigned g_actL[NMAX * 256];
__device__ unsigned g_WH[425984];
__device__ unsigned g_WL[425984];

// ================= CSR build ==================================================
__global__ void csr_zero(int n) {
    int i = blockIdx.x * blockDim.x + threadIdx.x;
    if (i < n) g_cnt[i] = 0;
}

__global__ void csr_hist(const int* __restrict__ ei, int E, int n) {
    int e = blockIdx.x * blockDim.x + threadIdx.x;
    if (e >= E + n) return;
    int dst = (e < E) ? ei[E + e] : e - E;
    atomicAdd(&g_cnt[dst], 1);
}

__global__ void csr_scan(int n, int Et) {
    __shared__ int part[1024];
    int tid = threadIdx.x;
    int chunk = (n + 1023) / 1024;
    int lo = tid * chunk;
    int hi = lo + chunk; if (hi > n) hi = n; if (lo > n) lo = n;
    int s = 0;
    for (int i = lo; i < hi; i++) s += g_cnt[i];
    part[tid] = s;
    __syncthreads();
    for (int off = 1; off < 1024; off <<= 1) {
        int v = (tid >= off) ? part[tid - off] : 0;
        __syncthreads();
        part[tid] += v;
        __syncthreads();
    }
    int run = (tid == 0) ? 0 : part[tid - 1];
    for (int i = lo; i < hi; i++) {
        g_rowptr[i] = run;
        g_cursor[i] = run;
        run += g_cnt[i];
    }
    if (tid == 1023) g_rowptr[n] = Et;
}

__global__ void csr_scatter(const int* __restrict__ ei, int E, int n) {
    int e = blockIdx.x * blockDim.x + threadIdx.x;
    if (e >= E + n) return;
    int src, dst;
    if (e < E) { src = ei[e]; dst = ei[E + e]; }
    else       { src = dst = e - E; }
    int pos = atomicAdd(&g_cursor[dst], 1);
    g_srcs[pos] = src;
}

// ================= misc ========================================================
__global__ void zero2(float* __restrict__ a, float* __restrict__ b, int n) {
    int i = blockIdx.x * blockDim.x + threadIdx.x;
    if (i < n) { a[i] = 0.f; b[i] = 0.f; }
}

// ================= bf16 split/pack helpers ====================================
__device__ __forceinline__ void split_pack2(float v0, float v1,
                                            unsigned& hw, unsigned& lw) {
    __nv_bfloat16 h0 = __float2bfloat16_rn(v0);
    __nv_bfloat16 h1 = __float2bfloat16_rn(v1);
    __nv_bfloat16 l0 = __float2bfloat16_rn(v0 - __bfloat162float(h0));
    __nv_bfloat16 l1 = __float2bfloat16_rn(v1 - __bfloat162float(h1));
    __nv_bfloat162 hp = __halves2bfloat162(h0, h1);
    __nv_bfloat162 lp = __halves2bfloat162(l0, l1);
    hw = *(unsigned*)&hp;
    lw = *(unsigned*)&lp;
}

// one launch packs all 4 weight matrices + the input activations
__global__ void pack_all(const float* __restrict__ W1, const float* __restrict__ fc1w,
                         const float* __restrict__ W2, const float* __restrict__ fc2w,
                         const float* __restrict__ x,
                         unsigned* __restrict__ wH, unsigned* __restrict__ wL,
                         unsigned* __restrict__ aH, unsigned* __restrict__ aL, int n)
{
    int t = blockIdx.x * blockDim.x + threadIdx.x;
    if (t < 106496) {
        const float* W; int off; int u = t;
        if (t < 8192)       { W = W1;   off = 0; }
        else if (t < 40960) { W = fc1w; off = 32768;  u = t - 8192; }
        else if (t < 73728) { W = W2;   off = 163840; u = t - 40960; }
        else                { W = fc2w; off = 294912; u = t - 73728; }
        int k2 = u >> 7;
        int n4 = u & 127;
        const float* p0 = W + (size_t)(2 * k2) * DIM + n4 * 4;
        const float* p1 = p0 + DIM;
        float4 a = *(const float4*)p0;
        float4 b = *(const float4*)p1;
        uint4 h, l;
        split_pack2(a.x, b.x, h.x, l.x);
        split_pack2(a.y, b.y, h.y, l.y);
        split_pack2(a.z, b.z, h.z, l.z);
        split_pack2(a.w, b.w, h.w, l.w);
        *(uint4*)(wH + off + (size_t)u * 4) = h;
        *(uint4*)(wL + off + (size_t)u * 4) = l;
    } else {
        int u = t - 106496;
        if (u >= n * 16) return;
        const float* p = x + (size_t)u * 8;
        float4 v0 = *(const float4*)p;
        float4 v1 = *(const float4*)(p + 4);
        uint4 h, l;
        split_pack2(v0.x, v0.y, h.x, l.x);
        split_pack2(v0.z, v0.w, h.y, l.y);
        split_pack2(v1.x, v1.y, h.z, l.z);
        split_pack2(v1.z, v1.w, h.w, l.w);
        *(uint4*)(aH + (size_t)u * 4) = h;
        *(uint4*)(aL + (size_t)u * 4) = l;
    }
}

// ================= BF16x3 GEMM (2-stage cp.async) + fused epilogues ===========
__device__ __forceinline__ void mma_bf16(float* d, const unsigned* a, const unsigned* b) {
    asm volatile(
        "mma.sync.aligned.m16n8k16.row.col.f32.bf16.bf16.f32 "
        "{%0,%1,%2,%3}, {%4,%5,%6,%7}, {%8,%9}, {%0,%1,%2,%3};"
        : "+f"(d[0]), "+f"(d[1]), "+f"(d[2]), "+f"(d[3])
        : "r"(a[0]), "r"(a[1]), "r"(a[2]), "r"(a[3]), "r"(b[0]), "r"(b[1]));
}

__device__ __forceinline__ void cp16(unsigned smem_addr, const void* gptr, int src_sz) {
    asm volatile("cp.async.ca.shared.global [%0], [%1], 16, %2;"
                 :: "r"(smem_addr), "l"(gptr), "r"(src_sz));
}

#define SA 12
#define SB 136

__global__ __launch_bounds__(256) void gemm_pk(
    const unsigned* __restrict__ AH, const unsigned* __restrict__ AL, int lda2,
    const unsigned* __restrict__ BH, const unsigned* __restrict__ BL,
    const float* __restrict__ bias, float* __restrict__ C,
    int M, int N, int K2, int has_bias, int do_relu,
    int attn_mode, const float* __restrict__ a_s, const float* __restrict__ a_d,
    float* __restrict__ als, float* __restrict__ ald, int do_stats)
{
    __shared__ unsigned sAH[2][128][SA];
    __shared__ unsigned sAL[2][128][SA];
    __shared__ unsigned sBH[2][8][SB];
    __shared__ unsigned sBL[2][8][SB];
    __shared__ float sm_ps[128][2], sm_pd[128][2];
    __shared__ float sm_cs[128], sm_cq[128];

    int tid  = threadIdx.x;
    int warp = tid >> 5;
    int lane = tid & 31;
    int grp  = lane >> 2;
    int l4   = lane & 3;

    int m0 = blockIdx.y * 128;
    int n0 = blockIdx.x * 128;
    int wm = (warp >> 2) * 64;
    int wn = (warp & 3) * 32;

    float acc[4][4][4];
#pragma unroll
    for (int mi = 0; mi < 4; mi++)
#pragma unroll
        for (int ni = 0; ni < 4; ni++)
#pragma unroll
            for (int r = 0; r < 4; r++) acc[mi][ni][r] = 0.f;

    int a_row = tid >> 1;
    int a_ch  = (tid & 1) * 4;
    int b_row = tid >> 5;
    int b_ch  = (tid & 31) * 4;
    int a_ok  = (m0 + a_row < M) ? 16 : 0;
    const unsigned* Arow_h = AH + (size_t)(m0 + a_row) * lda2 + a_ch;
    const unsigned* Arow_l = AL + (size_t)(m0 + a_row) * lda2 + a_ch;
    const unsigned* Brow_h = BH + (size_t)b_row * N + n0 + b_ch;
    const unsigned* Brow_l = BL + (size_t)b_row * N + n0 + b_ch;

    unsigned dAH = (unsigned)__cvta_generic_to_shared(&sAH[0][a_row][a_ch]);
    unsigned dAL = (unsigned)__cvta_generic_to_shared(&sAL[0][a_row][a_ch]);
    unsigned dBH = (unsigned)__cvta_generic_to_shared(&sBH[0][b_row][b_ch]);
    unsigned dBL = (unsigned)__cvta_generic_to_shared(&sBL[0][b_row][b_ch]);
    const unsigned stA = 128 * SA * 4;
    const unsigned stB = 8 * SB * 4;

    int nt = K2 >> 3;

    cp16(dAH, Arow_h, a_ok);
    cp16(dAL, Arow_l, a_ok);
    cp16(dBH, Brow_h, 16);
    cp16(dBL, Brow_l, 16);
    asm volatile("cp.async.commit_group;");

    int buf = 0;
    for (int t = 0; t < nt; t++) {
        if (t + 1 < nt) {
            int k2o = (t + 1) * 8;
            int nb = buf ^ 1;
            cp16(dAH + nb * stA, Arow_h + k2o, a_ok);
            cp16(dAL + nb * stA, Arow_l + k2o, a_ok);
            cp16(dBH + nb * stB, Brow_h + (size_t)k2o * N, 16);
            cp16(dBL + nb * stB, Brow_l + (size_t)k2o * N, 16);
            asm volatile("cp.async.commit_group;");
            asm volatile("cp.async.wait_group 1;");
        } else {
            asm volatile("cp.async.wait_group 0;");
        }
        __syncthreads();

        unsigned ah[4][4], al[4][4], bh[4][2], bl[4][2];
#pragma unroll
        for (int mi = 0; mi < 4; mi++) {
            int rm = wm + mi * 16 + grp;
            ah[mi][0] = sAH[buf][rm][l4];
            ah[mi][1] = sAH[buf][rm + 8][l4];
            ah[mi][2] = sAH[buf][rm][l4 + 4];
            ah[mi][3] = sAH[buf][rm + 8][l4 + 4];
            al[mi][0] = sAL[buf][rm][l4];
            al[mi][1] = sAL[buf][rm + 8][l4];
            al[mi][2] = sAL[buf][rm][l4 + 4];
            al[mi][3] = sAL[buf][rm + 8][l4 + 4];
        }
#pragma unroll
        for (int ni = 0; ni < 4; ni++) {
            int nn = wn + ni * 8 + grp;
            bh[ni][0] = sBH[buf][l4][nn];
            bh[ni][1] = sBH[buf][l4 + 4][nn];
            bl[ni][0] = sBL[buf][l4][nn];
            bl[ni][1] = sBL[buf][l4 + 4][nn];
        }
#pragma unroll
        for (int mi = 0; mi < 4; mi++)
#pragma unroll
            for (int ni = 0; ni < 4; ni++) {
                mma_bf16(acc[mi][ni], ah[mi], bh[ni]);
                mma_bf16(acc[mi][ni], ah[mi], bl[ni]);
                mma_bf16(acc[mi][ni], al[mi], bh[ni]);
            }
        __syncthreads();
        buf ^= 1;
    }

    // ---- fused epilogue ----
    int fused = (attn_mode != 0) || do_stats;
    if (fused) {
        if (tid < 128) {
            sm_ps[tid][0] = 0.f; sm_ps[tid][1] = 0.f;
            sm_pd[tid][0] = 0.f; sm_pd[tid][1] = 0.f;
            sm_cs[tid] = 0.f;    sm_cq[tid] = 0.f;
        }
        __syncthreads();
    }

    float as_c[8], ad_c[8];
    if (attn_mode) {
#pragma unroll
        for (int ni = 0; ni < 4; ni++) {
            int gc = n0 + wn + ni * 8 + l4 * 2;
            as_c[ni * 2] = a_s[gc];     as_c[ni * 2 + 1] = a_s[gc + 1];
            ad_c[ni * 2] = a_d[gc];     ad_c[ni * 2 + 1] = a_d[gc + 1];
        }
    }
    float ps[8], pd[8], cs[8], cq[8];
#pragma unroll
    for (int q = 0; q < 8; q++) { ps[q] = pd[q] = cs[q] = cq[q] = 0.f; }

#pragma unroll
    for (int mi = 0; mi < 4; mi++) {
        int r0 = m0 + wm + mi * 16 + grp;
        int r1 = r0 + 8;
        bool ok0 = (r0 < M), ok1 = (r1 < M);
#pragma unroll
        for (int ni = 0; ni < 4; ni++) {
            int c = n0 + wn + ni * 8 + l4 * 2;
            float2 v0 = make_float2(acc[mi][ni][0], acc[mi][ni][1]);
            float2 v1 = make_float2(acc[mi][ni][2], acc[mi][ni][3]);
            if (has_bias) {
                float2 bv = *(const float2*)(bias + c);
                v0.x += bv.x; v0.y += bv.y;
                v1.x += bv.x; v1.y += bv.y;
            }
            if (do_relu) {
                v0.x = fmaxf(v0.x, 0.f); v0.y = fmaxf(v0.y, 0.f);
                v1.x = fmaxf(v1.x, 0.f); v1.y = fmaxf(v1.y, 0.f);
            }
            if (attn_mode) {
                if (ok0) {
                    ps[mi * 2]     += v0.x * as_c[ni * 2] + v0.y * as_c[ni * 2 + 1];
                    pd[mi * 2]     += v0.x * ad_c[ni * 2] + v0.y * ad_c[ni * 2 + 1];
                }
                if (ok1) {
                    ps[mi * 2 + 1] += v1.x * as_c[ni * 2] + v1.y * as_c[ni * 2 + 1];
                    pd[mi * 2 + 1] += v1.x * ad_c[ni * 2] + v1.y * ad_c[ni * 2 + 1];
                }
            }
            if (do_stats) {
                float x0 = ok0 ? v0.x : 0.f, y0 = ok0 ? v0.y : 0.f;
                float x1 = ok1 ? v1.x : 0.f, y1 = ok1 ? v1.y : 0.f;
                cs[ni * 2]     += x0 + x1;
                cq[ni * 2]     += x0 * x0 + x1 * x1;
                cs[ni * 2 + 1] += y0 + y1;
                cq[ni * 2 + 1] += y0 * y0 + y1 * y1;
            }
            if (ok0) *(float2*)(C + (size_t)r0 * N + c) = v0;
            if (ok1) *(float2*)(C + (size_t)r1 * N + c) = v1;
        }
    }

    if (attn_mode) {
        int hsel = wn >> 6;
#pragma unroll
        for (int q = 0; q < 8; q++) {
            float vs = ps[q], vd = pd[q];
            vs += __shfl_xor_sync(0xffffffffu, vs, 1);
            vs += __shfl_xor_sync(0xffffffffu, vs, 2);
            vd += __shfl_xor_sync(0xffffffffu, vd, 1);
            vd += __shfl_xor_sync(0xffffffffu, vd, 2);
            if (l4 == 0) {
                int rt = wm + (q >> 1) * 16 + grp + (q & 1) * 8;
                atomicAdd(&sm_ps[rt][hsel], vs);
                atomicAdd(&sm_pd[rt][hsel], vd);
            }
        }
    }
    if (do_stats) {
#pragma unroll
        for (int q = 0; q < 8; q++) {
            float s = cs[q], sq = cq[q];
            s  += __shfl_xor_sync(0xffffffffu, s, 4);
            s  += __shfl_xor_sync(0xffffffffu, s, 8);
            s  += __shfl_xor_sync(0xffffffffu, s, 16);
            sq += __shfl_xor_sync(0xffffffffu, sq, 4);
            sq += __shfl_xor_sync(0xffffffffu, sq, 8);
            sq += __shfl_xor_sync(0xffffffffu, sq, 16);
            if (grp == 0) {
                int ct = wn + (q >> 1) * 8 + l4 * 2 + (q & 1);
                atomicAdd(&sm_cs[ct], s);
                atomicAdd(&sm_cq[ct], sq);
            }
        }
    }
    if (fused) {
        __syncthreads();
        if (tid < 128) {
            int gr = m0 + tid;
            if (attn_mode == 8 && gr < M) {
                int h0 = n0 >> 6;
                als[gr * 8 + h0]     = sm_ps[tid][0];
                als[gr * 8 + h0 + 1] = sm_ps[tid][1];
                ald[gr * 8 + h0]     = sm_pd[tid][0];
                ald[gr * 8 + h0 + 1] = sm_pd[tid][1];
            } else if (attn_mode == 1 && gr < M) {
                atomicAdd(&als[gr], sm_ps[tid][0] + sm_ps[tid][1]);
                atomicAdd(&ald[gr], sm_pd[tid][0] + sm_pd[tid][1]);
            }
            if (do_stats) {
                atomicAdd(&g_sum[n0 + tid], sm_cs[tid]);
                atomicAdd(&g_sumsq[n0 + tid], sm_cq[tid]);
            }
        }
    }
}

// ================= fused GAT softmax+aggregate v3 ==============================
// 2 thread-groups of 128: group g covers ALL 512 cols (float4) over the
// even(g=0)/odd(g=1) edges of each chunk -> serial edge chain halved.
#define CHUNK 128

__global__ __launch_bounds__(256) void gat_agg8(
    const float* __restrict__ h, const float* __restrict__ als,
    const float* __restrict__ ald, const float* __restrict__ bias,
    unsigned* __restrict__ outH, unsigned* __restrict__ outL)
{
    __shared__ int sh_src[CHUNK];
    __shared__ float sh_w[CHUNK][8];
    __shared__ float sh_mx[8], sh_inv[8], sh_ald[8];
    __shared__ float sh_part[128][4];

    int dst = blockIdx.x;
    int tid = threadIdx.x;
    int warp = tid >> 5;
    int lane = tid & 31;
    int r0 = g_rowptr[dst], r1 = g_rowptr[dst + 1];

    // stats: warp w computes softmax stats for head w
    {
        float aldv = ald[dst * 8 + warp];
        if (lane == 0) sh_ald[warp] = aldv;
        float mx = -1e30f;
        for (int i = r0 + lane; i < r1; i += 32) {
            int s = g_srcs[i];
            float ev = als[s * 8 + warp] + aldv;
            ev = (ev > 0.f) ? ev : 0.2f * ev;
            mx = fmaxf(mx, ev);
        }
#pragma unroll
        for (int o = 16; o; o >>= 1) mx = fmaxf(mx, __shfl_xor_sync(0xffffffffu, mx, o));
        float sum = 0.f;
        for (int i = r0 + lane; i < r1; i += 32) {
            int s = g_srcs[i];
            float ev = als[s * 8 + warp] + aldv;
            ev = (ev > 0.f) ? ev : 0.2f * ev;
            sum += __expf(ev - mx);
        }
#pragma unroll
        for (int o = 16; o; o >>= 1) sum += __shfl_xor_sync(0xffffffffu, sum, o);
        if (lane == 0) { sh_mx[warp] = mx; sh_inv[warp] = 1.f / sum; }
    }

    int eg = tid >> 7;          // edge-parity group: 0 or 1
    int ct = tid & 127;         // column-thread: 4 floats each
    int c4 = ct * 4;
    int hh = ct >> 4;           // head = c4/64
    float4 acc = make_float4(0.f, 0.f, 0.f, 0.f);

    for (int base = r0; base < r1; base += CHUNK) {
        int cnt = min(CHUNK, r1 - base);
        __syncthreads();
        if (tid < cnt) sh_src[tid] = g_srcs[base + tid];
        __syncthreads();
        for (int t = tid; t < cnt * 8; t += 256) {
            int i = t >> 3, hw = t & 7;
            int s = sh_src[i];
            float ev = als[s * 8 + hw] + sh_ald[hw];
            ev = (ev > 0.f) ? ev : 0.2f * ev;
            sh_w[i][hw] = __expf(ev - sh_mx[hw]) * sh_inv[hw];
        }
        __syncthreads();
        int i = eg;
        for (; i + 8 <= cnt; i += 8) {   // 4 edges of own parity per iter
            int s0 = sh_src[i],     s1 = sh_src[i + 2],
                s2 = sh_src[i + 4], s3 = sh_src[i + 6];
            float w0 = sh_w[i][hh],     w1 = sh_w[i + 2][hh],
                  w2 = sh_w[i + 4][hh], w3 = sh_w[i + 6][hh];
            float4 v0 = *(const float4*)(h + (size_t)s0 * DIM + c4);
            float4 v1 = *(const float4*)(h + (size_t)s1 * DIM + c4);
            float4 v2 = *(const float4*)(h + (size_t)s2 * DIM + c4);
            float4 v3 = *(const float4*)(h + (size_t)s3 * DIM + c4);
            acc.x = fmaf(w0, v0.x, acc.x); acc.y = fmaf(w0, v0.y, acc.y);
            acc.z = fmaf(w0, v0.z, acc.z); acc.w = fmaf(w0, v0.w, acc.w);
            acc.x = fmaf(w1, v1.x, acc.x); acc.y = fmaf(w1, v1.y, acc.y);
            acc.z = fmaf(w1, v1.z, acc.z); acc.w = fmaf(w1, v1.w, acc.w);
            acc.x = fmaf(w2, v2.x, acc.x); acc.y = fmaf(w2, v2.y, acc.y);
            acc.z = fmaf(w2, v2.z, acc.z); acc.w = fmaf(w2, v2.w, acc.w);
            acc.x = fmaf(w3, v3.x, acc.x); acc.y = fmaf(w3, v3.y, acc.y);
            acc.z = fmaf(w3, v3.z, acc.z); acc.w = fmaf(w3, v3.w, acc.w);
        }
        for (; i < cnt; i += 2) {
            int s = sh_src[i];
            float w = sh_w[i][hh];
            float4 v = *(const float4*)(h + (size_t)s * DIM + c4);
            acc.x = fmaf(w, v.x, acc.x); acc.y = fmaf(w, v.y, acc.y);
            acc.z = fmaf(w, v.z, acc.z); acc.w = fmaf(w, v.w, acc.w);
        }
    }

    if (eg == 1) {
        sh_part[ct][0] = acc.x; sh_part[ct][1] = acc.y;
        sh_part[ct][2] = acc.z; sh_part[ct][3] = acc.w;
    }
    __syncthreads();
    if (eg == 0) {
        acc.x += sh_part[ct][0]; acc.y += sh_part[ct][1];
        acc.z += sh_part[ct][2]; acc.w += sh_part[ct][3];
        float4 bv = *(const float4*)(bias + c4);
        acc.x += bv.x; acc.y += bv.y; acc.z += bv.z; acc.w += bv.w;
        unsigned h0, l0, h1, l1;
        split_pack2(acc.x, acc.y, h0, l0);
        split_pack2(acc.z, acc.w, h1, l1);
        int wi = dst * 256 + ct * 2;
        outH[wi] = h0; outL[wi] = l0;
        outH[wi + 1] = h1; outL[wi + 1] = l1;
    }
}

__global__ __launch_bounds__(256) void gat_agg1(
    const float* __restrict__ h, const float* __restrict__ als,
    const float* __restrict__ ald, const float* __restrict__ bias,
    unsigned* __restrict__ outH, unsigned* __restrict__ outL)
{
    __shared__ int sh_src[CHUNK];
    __shared__ float sh_w[CHUNK];
    __shared__ float sh_mx, sh_inv;
    __shared__ float sh_part[128][4];

    int dst = blockIdx.x;
    int tid = threadIdx.x;
    int r0 = g_rowptr[dst], r1 = g_rowptr[dst + 1];
    float aldv = ald[dst];

    if (tid < 32) {
        float mx = -1e30f;
        for (int i = r0 + tid; i < r1; i += 32) {
            int s = g_srcs[i];
            float ev = als[s] + aldv;
            ev = (ev > 0.f) ? ev : 0.2f * ev;
            mx = fmaxf(mx, ev);
        }
#pragma unroll
        for (int o = 16; o; o >>= 1) mx = fmaxf(mx, __shfl_xor_sync(0xffffffffu, mx, o));
        float sum = 0.f;
        for (int i = r0 + tid; i < r1; i += 32) {
            int s = g_srcs[i];
            float ev = als[s] + aldv;
            ev = (ev > 0.f) ? ev : 0.2f * ev;
            sum += __expf(ev - mx);
        }
#pragma unroll
        for (int o = 16; o; o >>= 1) sum += __shfl_xor_sync(0xffffffffu, sum, o);
        if (tid == 0) { sh_mx = mx; sh_inv = 1.f / sum; }
    }

    int eg = tid >> 7;
    int ct = tid & 127;
    int c4 = ct * 4;
    float4 acc = make_float4(0.f, 0.f, 0.f, 0.f);

    for (int base = r0; base < r1; base += CHUNK) {
        int cnt = min(CHUNK, r1 - base);
        __syncthreads();
        if (tid < cnt) sh_src[tid] = g_srcs[base + tid];
        __syncthreads();
        for (int t = tid; t < cnt; t += 256) {
            int s = sh_src[t];
            float ev = als[s] + aldv;
            ev = (ev > 0.f) ? ev : 0.2f * ev;
            sh_w[t] = __expf(ev - sh_mx) * sh_inv;
        }
        __syncthreads();
        int i = eg;
        for (; i + 8 <= cnt; i += 8) {
            int s0 = sh_src[i],     s1 = sh_src[i + 2],
                s2 = sh_src[i + 4], s3 = sh_src[i + 6];
            float w0 = sh_w[i],     w1 = sh_w[i + 2],
                  w2 = sh_w[i + 4], w3 = sh_w[i + 6];
            float4 v0 = *(const float4*)(h + (size_t)s0 * DIM + c4);
            float4 v1 = *(const float4*)(h + (size_t)s1 * DIM + c4);
            float4 v2 = *(const float4*)(h + (size_t)s2 * DIM + c4);
            float4 v3 = *(const float4*)(h + (size_t)s3 * DIM + c4);
            acc.x = fmaf(w0, v0.x, acc.x); acc.y = fmaf(w0, v0.y, acc.y);
            acc.z = fmaf(w0, v0.z, acc.z); acc.w = fmaf(w0, v0.w, acc.w);
            acc.x = fmaf(w1, v1.x, acc.x); acc.y = fmaf(w1, v1.y, acc.y);
            acc.z = fmaf(w1, v1.z, acc.z); acc.w = fmaf(w1, v1.w, acc.w);
            acc.x = fmaf(w2, v2.x, acc.x); acc.y = fmaf(w2, v2.y, acc.y);
            acc.z = fmaf(w2, v2.z, acc.z); acc.w = fmaf(w2, v2.w, acc.w);
            acc.x = fmaf(w3, v3.x, acc.x); acc.y = fmaf(w3, v3.y, acc.y);
            acc.z = fmaf(w3, v3.z, acc.z); acc.w = fmaf(w3, v3.w, acc.w);
        }
        for (; i < cnt; i += 2) {
            int s = sh_src[i];
            float w = sh_w[i];
            float4 v = *(const float4*)(h + (size_t)s * DIM + c4);
            acc.x = fmaf(w, v.x, acc.x); acc.y = fmaf(w, v.y, acc.y);
            acc.z = fmaf(w, v.z, acc.z); acc.w = fmaf(w, v.w, acc.w);
        }
    }

    if (eg == 1) {
        sh_part[ct][0] = acc.x; sh_part[ct][1] = acc.y;
        sh_part[ct][2] = acc.z; sh_part[ct][3] = acc.w;
    }
    __syncthreads();
    if (eg == 0) {
        acc.x += sh_part[ct][0]; acc.y += sh_part[ct][1];
        acc.z += sh_part[ct][2]; acc.w += sh_part[ct][3];
        float4 bv = *(const float4*)(bias + c4);
        acc.x += bv.x; acc.y += bv.y; acc.z += bv.z; acc.w += bv.w;
        unsigned h0, l0, h1, l1;
        split_pack2(acc.x, acc.y, h0, l0);
        split_pack2(acc.z, acc.w, h1, l1);
        int wi = dst * 256 + ct * 2;
        outH[wi] = h0; outL[wi] = l0;
        outH[wi + 1] = h1; outL[wi + 1] = l1;
    }
}

// ================= BN apply (+ optional fused final linear) ===================
__global__ __launch_bounds__(256) void bn_apply(
    const float* __restrict__ x,
    const float* __restrict__ gamma, const float* __restrict__ beta,
    unsigned* __restrict__ outH, unsigned* __restrict__ outL,
    const float* __restrict__ linw, const float* __restrict__ linb,
    float* __restrict__ out, int n, int mode)
{
    __shared__ float rs[8][2];
    int row = blockIdx.x;
    int c2 = threadIdx.x;
    int col = c2 * 2;
    float inv_n = 1.f / (float)n;
    float mu0 = g_sum[col] * inv_n;
    float mu1 = g_sum[col + 1] * inv_n;
    float var0 = g_sumsq[col] * inv_n - mu0 * mu0;
    float var1 = g_sumsq[col + 1] * inv_n - mu1 * mu1;
    float2 xv = *(const float2*)(x + (size_t)row * DIM + col);
    float y0 = fmaf(gamma[col] * (xv.x - mu0), rsqrtf(var0 + 1e-5f), beta[col]);
    float y1 = fmaf(gamma[col + 1] * (xv.y - mu1), rsqrtf(var1 + 1e-5f), beta[col + 1]);

    if (mode == 0) {
        unsigned hw, lw;
        split_pack2(y0, y1, hw, lw);
        int wi = row * 256 + c2;
        outH[wi] = hw; outL[wi] = lw;
    } else {
        float p0 = y0 * linw[col * 2]     + y1 * linw[col * 2 + 2];
        float p1 = y0 * linw[col * 2 + 1] + y1 * linw[col * 2 + 3];
#pragma unroll
        for (int o = 16; o; o >>= 1) {
            p0 += __shfl_down_sync(0xffffffffu, p0, o);
            p1 += __shfl_down_sync(0xffffffffu, p1, o);
        }
        int warp = c2 >> 5, lane = c2 & 31;
        if (lane == 0) { rs[warp][0] = p0; rs[warp][1] = p1; }
        __syncthreads();
        if (c2 == 0) {
            float s0 = 0.f, s1 = 0.f;
#pragma unroll
            for (int w = 0; w < 8; w++) { s0 += rs[w][0]; s1 += rs[w][1]; }
            out[row * 2 + 0] = fmaxf(s0 + linb[0], 0.f);
            out[row * 2 + 1] = fmaxf(s1 + linb[1], 0.f);
        }
    }
}

// ------------------------------------------------------------------------------
extern "C" void kernel_launch(void* const* d_in, const int* in_sizes, int n_in,
                              void* d_out, int out_size)
{
    const float* x    = (const float*)d_in[0];
    const int*   ei   = (const int*)d_in[1];
    const float* W1   = (const float*)d_in[2];
    const float* a1s  = (const float*)d_in[3];
    const float* a1d  = (const float*)d_in[4];
    const float* b1   = (const float*)d_in[5];
    const float* W2   = (const float*)d_in[6];
    const float* a2s  = (const float*)d_in[7];
    const float* a2d  = (const float*)d_in[8];
    const float* b2   = (const float*)d_in[9];
    const float* fc1w = (const float*)d_in[10];
    const float* fc1b = (const float*)d_in[11];
    const float* g1   = (const float*)d_in[12];
    const float* be1  = (const float*)d_in[13];
    const float* fc2w = (const float*)d_in[14];
    const float* fc2b = (const float*)d_in[15];
    const float* g2   = (const float*)d_in[16];
    const float* be2  = (const float*)d_in[17];
    const float* linw = (const float*)d_in[18];
    const float* linb = (const float*)d_in[19];
    float* out = (float*)d_out;

    int n = out_size / 2;        // 20000
    int E = in_sizes[1] / 2;     // 320000
    int Et = E + n;

    float *A, *C, *als, *ald, *sum, *sumsq;
    unsigned *aH, *aL, *wH, *wL;
    cudaGetSymbolAddress((void**)&A,     g_bufA);
    cudaGetSymbolAddress((void**)&C,     g_bufC);
    cudaGetSymbolAddress((void**)&als,   g_als);
    cudaGetSymbolAddress((void**)&ald,   g_ald);
    cudaGetSymbolAddress((void**)&sum,   g_sum);
    cudaGetSymbolAddress((void**)&sumsq, g_sumsq);
    cudaGetSymbolAddress((void**)&aH,    g_actH);
    cudaGetSymbolAddress((void**)&aL,    g_actL);
    cudaGetSymbolAddress((void**)&wH,    g_WH);
    cudaGetSymbolAddress((void**)&wL,    g_WL);

    const int OW1 = 0, OF1 = 32768, OW2 = 163840, OF2 = 294912;

    dim3 gemm_grid(DIM / 128, (n + 127) / 128);

    // ---------------- CSR build ----------------
    csr_zero<<<(n + 255) / 256, 256>>>(n);
    csr_hist<<<(Et + 255) / 256, 256>>>(ei, E, n);
    csr_scan<<<1, 1024>>>(n, Et);
    csr_scatter<<<(Et + 255) / 256, 256>>>(ei, E, n);

    // ---------------- pack weights + input (single launch) ----------------
    pack_all<<<(106496 + n * 16 + 255) / 256, 256>>>(W1, fc1w, W2, fc2w, x,
                                                     wH, wL, aH, aL, n);

    // ---------------- layer 1: GATConv(128 -> 8x64), attn fused ----------------
    gemm_pk<<<gemm_grid, 256>>>(aH, aL, 64, wH + OW1, wL + OW1, nullptr, A,
                                n, DIM, 64, 0, 0, 8, a1s, a1d, als, ald, 0);
    gat_agg8<<<n, 256>>>(A, als, ald, b1, aH, aL);

    // ---------------- fc1 + relu + BN (stats fused) ----------------
    zero2<<<2, 256>>>(sum, sumsq, DIM);
    gemm_pk<<<gemm_grid, 256>>>(aH, aL, 256, wH + OF1, wL + OF1, fc1b, C,
                                n, DIM, 256, 1, 1, 0, nullptr, nullptr, nullptr, nullptr, 1);
    bn_apply<<<n, 256>>>(C, g1, be1, aH, aL, nullptr, nullptr, nullptr, n, 0);

    // ---------------- layer 2: GATConv(512 -> 1x512), attn fused (atomic) ------
    zero2<<<(n + 255) / 256, 256>>>(als, ald, n);
    gemm_pk<<<gemm_grid, 256>>>(aH, aL, 256, wH + OW2, wL + OW2, nullptr, A,
                                n, DIM, 256, 0, 0, 1, a2s, a2d, als, ald, 0);
    gat_agg1<<<n, 256>>>(A, als, ald, b2, aH, aL);

    // ---------------- fc2 + relu + BN (stats fused) + final linear -------------
    zero2<<<2, 256>>>(sum, sumsq, DIM);
    gemm_pk<<<gemm_grid, 256>>>(aH, aL, 256, wH + OF2, wL + OF2, fc2b, C,
                                n, DIM, 256, 1, 1, 0, nullptr, nullptr, nullptr, nullptr, 1);
    bn_apply<<<n, 256>>>(C, g2, be2, nullptr, nullptr, linw, linb, out, n, 1);
}

// round 13
// speedup vs baseline: 1.0277x; 1.0144x over previous
#include <cuda_runtime.h>
#include <cuda_bf16.h>
#include <math.h>

#define NMAX 20000
#define EMAX 320000
#define ETMAX (NMAX + EMAX)
#define DIM 512
#define H1 8
#define C1 64

// ---------------- scratch (static device memory; no allocations) -------------
__device__ float g_bufA[NMAX * DIM];   // GEMM fp32 outputs
__device__ float g_bufC[NMAX * DIM];   // fc output (post-relu) for BN
__device__ float g_als[NMAX * H1];
__device__ float g_ald[NMAX * H1];
__device__ float g_als2[NMAX];
__device__ float g_ald2[NMAX];
__device__ float g_stats[2048];        // [sum1|sumsq1|sum2|sumsq2] x 512
__device__ int g_cnt[NMAX];
__device__ int g_rowptr[NMAX + 1];
__device__ int g_cursor[NMAX];
__device__ int g_srcs[ETMAX];
// packed bf16 hi/lo operands
__device__ unsigned g_actH[NMAX * 256];
__device__ unsigned g_actL[NMAX * 256];
__device__ unsigned g_WH[425984];
__device__ unsigned g_WL[425984];

// ================= CSR build ==================================================
__global__ void csr_zero(int n) {
    int i = blockIdx.x * blockDim.x + threadIdx.x;
    if (i < n) g_cnt[i] = 0;
}

__global__ void csr_hist(const int* __restrict__ ei, int E, int n) {
    int e = blockIdx.x * blockDim.x + threadIdx.x;
    if (e >= E + n) return;
    int dst = (e < E) ? ei[E + e] : e - E;
    atomicAdd(&g_cnt[dst], 1);
}

__global__ void csr_scan(int n, int Et) {
    __shared__ int part[1024];
    int tid = threadIdx.x;
    int chunk = (n + 1023) / 1024;
    int lo = tid * chunk;
    int hi = lo + chunk; if (hi > n) hi = n; if (lo > n) lo = n;
    int s = 0;
    for (int i = lo; i < hi; i++) s += g_cnt[i];
    part[tid] = s;
    __syncthreads();
    for (int off = 1; off < 1024; off <<= 1) {
        int v = (tid >= off) ? part[tid - off] : 0;
        __syncthreads();
        part[tid] += v;
        __syncthreads();
    }
    int run = (tid == 0) ? 0 : part[tid - 1];
    for (int i = lo; i < hi; i++) {
        g_rowptr[i] = run;
        g_cursor[i] = run;
        run += g_cnt[i];
    }
    if (tid == 1023) g_rowptr[n] = Et;
}

__global__ void csr_scatter(const int* __restrict__ ei, int E, int n) {
    int e = blockIdx.x * blockDim.x + threadIdx.x;
    if (e >= E + n) return;
    int src, dst;
    if (e < E) { src = ei[e]; dst = ei[E + e]; }
    else       { src = dst = e - E; }
    int pos = atomicAdd(&g_cursor[dst], 1);
    g_srcs[pos] = src;
}

// zero layer2 attn buffers + all BN stat buffers in one launch
__global__ void zero_aux(float* __restrict__ als2, float* __restrict__ ald2,
                         float* __restrict__ stats, int n)
{
    int i = blockIdx.x * blockDim.x + threadIdx.x;
    if (i < n) { als2[i] = 0.f; ald2[i] = 0.f; }
    if (i < 2048) stats[i] = 0.f;
}

// ================= bf16 split/pack helpers ====================================
__device__ __forceinline__ void split_pack2(float v0, float v1,
                                            unsigned& hw, unsigned& lw) {
    __nv_bfloat16 h0 = __float2bfloat16_rn(v0);
    __nv_bfloat16 h1 = __float2bfloat16_rn(v1);
    __nv_bfloat16 l0 = __float2bfloat16_rn(v0 - __bfloat162float(h0));
    __nv_bfloat16 l1 = __float2bfloat16_rn(v1 - __bfloat162float(h1));
    __nv_bfloat162 hp = __halves2bfloat162(h0, h1);
    __nv_bfloat162 lp = __halves2bfloat162(l0, l1);
    hw = *(unsigned*)&hp;
    lw = *(unsigned*)&lp;
}

// one launch packs all 4 weight matrices + the input activations
__global__ void pack_all(const float* __restrict__ W1, const float* __restrict__ fc1w,
                         const float* __restrict__ W2, const float* __restrict__ fc2w,
                         const float* __restrict__ x,
                         unsigned* __restrict__ wH, unsigned* __restrict__ wL,
                         unsigned* __restrict__ aH, unsigned* __restrict__ aL, int n)
{
    int t = blockIdx.x * blockDim.x + threadIdx.x;
    if (t < 106496) {
        const float* W; int off; int u = t;
        if (t < 8192)       { W = W1;   off = 0; }
        else if (t < 40960) { W = fc1w; off = 32768;  u = t - 8192; }
        else if (t < 73728) { W = W2;   off = 163840; u = t - 40960; }
        else                { W = fc2w; off = 294912; u = t - 73728; }
        int k2 = u >> 7;
        int n4 = u & 127;
        const float* p0 = W + (size_t)(2 * k2) * DIM + n4 * 4;
        const float* p1 = p0 + DIM;
        float4 a = *(const float4*)p0;
        float4 b = *(const float4*)p1;
        uint4 h, l;
        split_pack2(a.x, b.x, h.x, l.x);
        split_pack2(a.y, b.y, h.y, l.y);
        split_pack2(a.z, b.z, h.z, l.z);
        split_pack2(a.w, b.w, h.w, l.w);
        *(uint4*)(wH + off + (size_t)u * 4) = h;
        *(uint4*)(wL + off + (size_t)u * 4) = l;
    } else {
        int u = t - 106496;
        if (u >= n * 16) return;
        const float* p = x + (size_t)u * 8;
        float4 v0 = *(const float4*)p;
        float4 v1 = *(const float4*)(p + 4);
        uint4 h, l;
        split_pack2(v0.x, v0.y, h.x, l.x);
        split_pack2(v0.z, v0.w, h.y, l.y);
        split_pack2(v1.x, v1.y, h.z, l.z);
        split_pack2(v1.z, v1.w, h.w, l.w);
        *(uint4*)(aH + (size_t)u * 4) = h;
        *(uint4*)(aL + (size_t)u * 4) = l;
    }
}

// ================= BF16x3 GEMM (2-stage cp.async) + fused epilogues ===========
__device__ __forceinline__ void mma_bf16(float* d, const unsigned* a, const unsigned* b) {
    asm volatile(
        "mma.sync.aligned.m16n8k16.row.col.f32.bf16.bf16.f32 "
        "{%0,%1,%2,%3}, {%4,%5,%6,%7}, {%8,%9}, {%0,%1,%2,%3};"
        : "+f"(d[0]), "+f"(d[1]), "+f"(d[2]), "+f"(d[3])
        : "r"(a[0]), "r"(a[1]), "r"(a[2]), "r"(a[3]), "r"(b[0]), "r"(b[1]));
}

__device__ __forceinline__ void cp16(unsigned smem_addr, const void* gptr, int src_sz) {
    asm volatile("cp.async.ca.shared.global [%0], [%1], 16, %2;"
                 :: "r"(smem_addr), "l"(gptr), "r"(src_sz));
}

#define SA 12
#define SB 136

__global__ __launch_bounds__(256) void gemm_pk(
    const unsigned* __restrict__ AH, const unsigned* __restrict__ AL, int lda2,
    const unsigned* __restrict__ BH, const unsigned* __restrict__ BL,
    const float* __restrict__ bias, float* __restrict__ C,
    int M, int N, int K2, int has_bias, int do_relu,
    int attn_mode, const float* __restrict__ a_s, const float* __restrict__ a_d,
    float* __restrict__ als, float* __restrict__ ald,
    int do_stats, float* __restrict__ sumP, float* __restrict__ sumsqP)
{
    __shared__ unsigned sAH[2][128][SA];
    __shared__ unsigned sAL[2][128][SA];
    __shared__ unsigned sBH[2][8][SB];
    __shared__ unsigned sBL[2][8][SB];
    __shared__ float sm_ps[128][2], sm_pd[128][2];
    __shared__ float sm_cs[128], sm_cq[128];

    int tid  = threadIdx.x;
    int warp = tid >> 5;
    int lane = tid & 31;
    int grp  = lane >> 2;
    int l4   = lane & 3;

    int m0 = blockIdx.y * 128;
    int n0 = blockIdx.x * 128;
    int wm = (warp >> 2) * 64;
    int wn = (warp & 3) * 32;

    float acc[4][4][4];
#pragma unroll
    for (int mi = 0; mi < 4; mi++)
#pragma unroll
        for (int ni = 0; ni < 4; ni++)
#pragma unroll
            for (int r = 0; r < 4; r++) acc[mi][ni][r] = 0.f;

    int a_row = tid >> 1;
    int a_ch  = (tid & 1) * 4;
    int b_row = tid >> 5;
    int b_ch  = (tid & 31) * 4;
    int a_ok  = (m0 + a_row < M) ? 16 : 0;
    const unsigned* Arow_h = AH + (size_t)(m0 + a_row) * lda2 + a_ch;
    const unsigned* Arow_l = AL + (size_t)(m0 + a_row) * lda2 + a_ch;
    const unsigned* Brow_h = BH + (size_t)b_row * N + n0 + b_ch;
    const unsigned* Brow_l = BL + (size_t)b_row * N + n0 + b_ch;

    unsigned dAH = (unsigned)__cvta_generic_to_shared(&sAH[0][a_row][a_ch]);
    unsigned dAL = (unsigned)__cvta_generic_to_shared(&sAL[0][a_row][a_ch]);
    unsigned dBH = (unsigned)__cvta_generic_to_shared(&sBH[0][b_row][b_ch]);
    unsigned dBL = (unsigned)__cvta_generic_to_shared(&sBL[0][b_row][b_ch]);
    const unsigned stA = 128 * SA * 4;
    const unsigned stB = 8 * SB * 4;

    int nt = K2 >> 3;

    cp16(dAH, Arow_h, a_ok);
    cp16(dAL, Arow_l, a_ok);
    cp16(dBH, Brow_h, 16);
    cp16(dBL, Brow_l, 16);
    asm volatile("cp.async.commit_group;");

    int buf = 0;
    for (int t = 0; t < nt; t++) {
        if (t + 1 < nt) {
            int k2o = (t + 1) * 8;
            int nb = buf ^ 1;
            cp16(dAH + nb * stA, Arow_h + k2o, a_ok);
            cp16(dAL + nb * stA, Arow_l + k2o, a_ok);
            cp16(dBH + nb * stB, Brow_h + (size_t)k2o * N, 16);
            cp16(dBL + nb * stB, Brow_l + (size_t)k2o * N, 16);
            asm volatile("cp.async.commit_group;");
            asm volatile("cp.async.wait_group 1;");
        } else {
            asm volatile("cp.async.wait_group 0;");
        }
        __syncthreads();

        unsigned ah[4][4], al[4][4], bh[4][2], bl[4][2];
#pragma unroll
        for (int mi = 0; mi < 4; mi++) {
            int rm = wm + mi * 16 + grp;
            ah[mi][0] = sAH[buf][rm][l4];
            ah[mi][1] = sAH[buf][rm + 8][l4];
            ah[mi][2] = sAH[buf][rm][l4 + 4];
            ah[mi][3] = sAH[buf][rm + 8][l4 + 4];
            al[mi][0] = sAL[buf][rm][l4];
            al[mi][1] = sAL[buf][rm + 8][l4];
            al[mi][2] = sAL[buf][rm][l4 + 4];
            al[mi][3] = sAL[buf][rm + 8][l4 + 4];
        }
#pragma unroll
        for (int ni = 0; ni < 4; ni++) {
            int nn = wn + ni * 8 + grp;
            bh[ni][0] = sBH[buf][l4][nn];
            bh[ni][1] = sBH[buf][l4 + 4][nn];
            bl[ni][0] = sBL[buf][l4][nn];
            bl[ni][1] = sBL[buf][l4 + 4][nn];
        }
#pragma unroll
        for (int mi = 0; mi < 4; mi++)
#pragma unroll
            for (int ni = 0; ni < 4; ni++) {
                mma_bf16(acc[mi][ni], ah[mi], bh[ni]);
                mma_bf16(acc[mi][ni], ah[mi], bl[ni]);
                mma_bf16(acc[mi][ni], al[mi], bh[ni]);
            }
        __syncthreads();
        buf ^= 1;
    }

    // ---- fused epilogue ----
    int fused = (attn_mode != 0) || do_stats;
    if (fused) {
        if (tid < 128) {
            sm_ps[tid][0] = 0.f; sm_ps[tid][1] = 0.f;
            sm_pd[tid][0] = 0.f; sm_pd[tid][1] = 0.f;
            sm_cs[tid] = 0.f;    sm_cq[tid] = 0.f;
        }
        __syncthreads();
    }

    float as_c[8], ad_c[8];
    if (attn_mode) {
#pragma unroll
        for (int ni = 0; ni < 4; ni++) {
            int gc = n0 + wn + ni * 8 + l4 * 2;
            as_c[ni * 2] = a_s[gc];     as_c[ni * 2 + 1] = a_s[gc + 1];
            ad_c[ni * 2] = a_d[gc];     ad_c[ni * 2 + 1] = a_d[gc + 1];
        }
    }
    float ps[8], pd[8], cs[8], cq[8];
#pragma unroll
    for (int q = 0; q < 8; q++) { ps[q] = pd[q] = cs[q] = cq[q] = 0.f; }

#pragma unroll
    for (int mi = 0; mi < 4; mi++) {
        int r0 = m0 + wm + mi * 16 + grp;
        int r1 = r0 + 8;
        bool ok0 = (r0 < M), ok1 = (r1 < M);
#pragma unroll
        for (int ni = 0; ni < 4; ni++) {
            int c = n0 + wn + ni * 8 + l4 * 2;
            float2 v0 = make_float2(acc[mi][ni][0], acc[mi][ni][1]);
            float2 v1 = make_float2(acc[mi][ni][2], acc[mi][ni][3]);
            if (has_bias) {
                float2 bv = *(const float2*)(bias + c);
                v0.x += bv.x; v0.y += bv.y;
                v1.x += bv.x; v1.y += bv.y;
            }
            if (do_relu) {
                v0.x = fmaxf(v0.x, 0.f); v0.y = fmaxf(v0.y, 0.f);
                v1.x = fmaxf(v1.x, 0.f); v1.y = fmaxf(v1.y, 0.f);
            }
            if (attn_mode) {
                if (ok0) {
                    ps[mi * 2]     += v0.x * as_c[ni * 2] + v0.y * as_c[ni * 2 + 1];
                    pd[mi * 2]     += v0.x * ad_c[ni * 2] + v0.y * ad_c[ni * 2 + 1];
                }
                if (ok1) {
                    ps[mi * 2 + 1] += v1.x * as_c[ni * 2] + v1.y * as_c[ni * 2 + 1];
                    pd[mi * 2 + 1] += v1.x * ad_c[ni * 2] + v1.y * ad_c[ni * 2 + 1];
                }
            }
            if (do_stats) {
                float x0 = ok0 ? v0.x : 0.f, y0 = ok0 ? v0.y : 0.f;
                float x1 = ok1 ? v1.x : 0.f, y1 = ok1 ? v1.y : 0.f;
                cs[ni * 2]     += x0 + x1;
                cq[ni * 2]     += x0 * x0 + x1 * x1;
                cs[ni * 2 + 1] += y0 + y1;
                cq[ni * 2 + 1] += y0 * y0 + y1 * y1;
            }
            if (ok0) *(float2*)(C + (size_t)r0 * N + c) = v0;
            if (ok1) *(float2*)(C + (size_t)r1 * N + c) = v1;
        }
    }

    if (attn_mode) {
        int hsel = wn >> 6;
#pragma unroll
        for (int q = 0; q < 8; q++) {
            float vs = ps[q], vd = pd[q];
            vs += __shfl_xor_sync(0xffffffffu, vs, 1);
            vs += __shfl_xor_sync(0xffffffffu, vs, 2);
            vd += __shfl_xor_sync(0xffffffffu, vd, 1);
            vd += __shfl_xor_sync(0xffffffffu, vd, 2);
            if (l4 == 0) {
                int rt = wm + (q >> 1) * 16 + grp + (q & 1) * 8;
                atomicAdd(&sm_ps[rt][hsel], vs);
                atomicAdd(&sm_pd[rt][hsel], vd);
            }
        }
    }
    if (do_stats) {
#pragma unroll
        for (int q = 0; q < 8; q++) {
            float s = cs[q], sq = cq[q];
            s  += __shfl_xor_sync(0xffffffffu, s, 4);
            s  += __shfl_xor_sync(0xffffffffu, s, 8);
            s  += __shfl_xor_sync(0xffffffffu, s, 16);
            sq += __shfl_xor_sync(0xffffffffu, sq, 4);
            sq += __shfl_xor_sync(0xffffffffu, sq, 8);
            sq += __shfl_xor_sync(0xffffffffu, sq, 16);
            if (grp == 0) {
                int ct = wn + (q >> 1) * 8 + l4 * 2 + (q & 1);
                atomicAdd(&sm_cs[ct], s);
                atomicAdd(&sm_cq[ct], sq);
            }
        }
    }
    if (fused) {
        __syncthreads();
        if (tid < 128) {
            int gr = m0 + tid;
            if (attn_mode == 8 && gr < M) {
                int h0 = n0 >> 6;
                als[gr * 8 + h0]     = sm_ps[tid][0];
                als[gr * 8 + h0 + 1] = sm_ps[tid][1];
                ald[gr * 8 + h0]     = sm_pd[tid][0];
                ald[gr * 8 + h0 + 1] = sm_pd[tid][1];
            } else if (attn_mode == 1 && gr < M) {
                atomicAdd(&als[gr], sm_ps[tid][0] + sm_ps[tid][1]);
                atomicAdd(&ald[gr], sm_pd[tid][0] + sm_pd[tid][1]);
            }
            if (do_stats) {
                atomicAdd(&sumP[n0 + tid], sm_cs[tid]);
                atomicAdd(&sumsqP[n0 + tid], sm_cq[tid]);
            }
        }
    }
}

// ================= fused GAT softmax+aggregate v3 ==============================
#define CHUNK 128

__global__ __launch_bounds__(256) void gat_agg8(
    const float* __restrict__ h, const float* __restrict__ als,
    const float* __restrict__ ald, const float* __restrict__ bias,
    unsigned* __restrict__ outH, unsigned* __restrict__ outL)
{
    __shared__ int sh_src[CHUNK];
    __shared__ float sh_w[CHUNK][8];
    __shared__ float sh_mx[8], sh_inv[8], sh_ald[8];
    __shared__ float sh_part[128][4];

    int dst = blockIdx.x;
    int tid = threadIdx.x;
    int warp = tid >> 5;
    int lane = tid & 31;
    int r0 = g_rowptr[dst], r1 = g_rowptr[dst + 1];

    {
        float aldv = ald[dst * 8 + warp];
        if (lane == 0) sh_ald[warp] = aldv;
        float mx = -1e30f;
        for (int i = r0 + lane; i < r1; i += 32) {
            int s = g_srcs[i];
            float ev = als[s * 8 + warp] + aldv;
            ev = (ev > 0.f) ? ev : 0.2f * ev;
            mx = fmaxf(mx, ev);
        }
#pragma unroll
        for (int o = 16; o; o >>= 1) mx = fmaxf(mx, __shfl_xor_sync(0xffffffffu, mx, o));
        float sum = 0.f;
        for (int i = r0 + lane; i < r1; i += 32) {
            int s = g_srcs[i];
            float ev = als[s * 8 + warp] + aldv;
            ev = (ev > 0.f) ? ev : 0.2f * ev;
            sum += __expf(ev - mx);
        }
#pragma unroll
        for (int o = 16; o; o >>= 1) sum += __shfl_xor_sync(0xffffffffu, sum, o);
        if (lane == 0) { sh_mx[warp] = mx; sh_inv[warp] = 1.f / sum; }
    }

    int eg = tid >> 7;
    int ct = tid & 127;
    int c4 = ct * 4;
    int hh = ct >> 4;
    float4 acc = make_float4(0.f, 0.f, 0.f, 0.f);

    for (int base = r0; base < r1; base += CHUNK) {
        int cnt = min(CHUNK, r1 - base);
        __syncthreads();
        if (tid < cnt) sh_src[tid] = g_srcs[base + tid];
        __syncthreads();
        for (int t = tid; t < cnt * 8; t += 256) {
            int i = t >> 3, hw = t & 7;
            int s = sh_src[i];
            float ev = als[s * 8 + hw] + sh_ald[hw];
            ev = (ev > 0.f) ? ev : 0.2f * ev;
            sh_w[i][hw] = __expf(ev - sh_mx[hw]) * sh_inv[hw];
        }
        __syncthreads();
        int i = eg;
        for (; i + 8 <= cnt; i += 8) {
            int s0 = sh_src[i],     s1 = sh_src[i + 2],
                s2 = sh_src[i + 4], s3 = sh_src[i + 6];
            float w0 = sh_w[i][hh],     w1 = sh_w[i + 2][hh],
                  w2 = sh_w[i + 4][hh], w3 = sh_w[i + 6][hh];
            float4 v0 = *(const float4*)(h + (size_t)s0 * DIM + c4);
            float4 v1 = *(const float4*)(h + (size_t)s1 * DIM + c4);
            float4 v2 = *(const float4*)(h + (size_t)s2 * DIM + c4);
            float4 v3 = *(const float4*)(h + (size_t)s3 * DIM + c4);
            acc.x = fmaf(w0, v0.x, acc.x); acc.y = fmaf(w0, v0.y, acc.y);
            acc.z = fmaf(w0, v0.z, acc.z); acc.w = fmaf(w0, v0.w, acc.w);
            acc.x = fmaf(w1, v1.x, acc.x); acc.y = fmaf(w1, v1.y, acc.y);
            acc.z = fmaf(w1, v1.z, acc.z); acc.w = fmaf(w1, v1.w, acc.w);
            acc.x = fmaf(w2, v2.x, acc.x); acc.y = fmaf(w2, v2.y, acc.y);
            acc.z = fmaf(w2, v2.z, acc.z); acc.w = fmaf(w2, v2.w, acc.w);
            acc.x = fmaf(w3, v3.x, acc.x); acc.y = fmaf(w3, v3.y, acc.y);
            acc.z = fmaf(w3, v3.z, acc.z); acc.w = fmaf(w3, v3.w, acc.w);
        }
        for (; i < cnt; i += 2) {
            int s = sh_src[i];
            float w = sh_w[i][hh];
            float4 v = *(const float4*)(h + (size_t)s * DIM + c4);
            acc.x = fmaf(w, v.x, acc.x); acc.y = fmaf(w, v.y, acc.y);
            acc.z = fmaf(w, v.z, acc.z); acc.w = fmaf(w, v.w, acc.w);
        }
    }

    if (eg == 1) {
        sh_part[ct][0] = acc.x; sh_part[ct][1] = acc.y;
        sh_part[ct][2] = acc.z; sh_part[ct][3] = acc.w;
    }
    __syncthreads();
    if (eg == 0) {
        acc.x += sh_part[ct][0]; acc.y += sh_part[ct][1];
        acc.z += sh_part[ct][2]; acc.w += sh_part[ct][3];
        float4 bv = *(const float4*)(bias + c4);
        acc.x += bv.x; acc.y += bv.y; acc.z += bv.z; acc.w += bv.w;
        unsigned h0, l0, h1, l1;
        split_pack2(acc.x, acc.y, h0, l0);
        split_pack2(acc.z, acc.w, h1, l1);
        int wi = dst * 256 + ct * 2;
        outH[wi] = h0; outL[wi] = l0;
        outH[wi + 1] = h1; outL[wi + 1] = l1;
    }
}

__global__ __launch_bounds__(256) void gat_agg1(
    const float* __restrict__ h, const float* __restrict__ als,
    const float* __restrict__ ald, const float* __restrict__ bias,
    unsigned* __restrict__ outH, unsigned* __restrict__ outL)
{
    __shared__ int sh_src[CHUNK];
    __shared__ float sh_w[CHUNK];
    __shared__ float sh_mx, sh_inv;
    __shared__ float sh_part[128][4];

    int dst = blockIdx.x;
    int tid = threadIdx.x;
    int r0 = g_rowptr[dst], r1 = g_rowptr[dst + 1];
    float aldv = ald[dst];

    if (tid < 32) {
        float mx = -1e30f;
        for (int i = r0 + tid; i < r1; i += 32) {
            int s = g_srcs[i];
            float ev = als[s] + aldv;
            ev = (ev > 0.f) ? ev : 0.2f * ev;
            mx = fmaxf(mx, ev);
        }
#pragma unroll
        for (int o = 16; o; o >>= 1) mx = fmaxf(mx, __shfl_xor_sync(0xffffffffu, mx, o));
        float sum = 0.f;
        for (int i = r0 + tid; i < r1; i += 32) {
            int s = g_srcs[i];
            float ev = als[s] + aldv;
            ev = (ev > 0.f) ? ev : 0.2f * ev;
            sum += __expf(ev - mx);
        }
#pragma unroll
        for (int o = 16; o; o >>= 1) sum += __shfl_xor_sync(0xffffffffu, sum, o);
        if (tid == 0) { sh_mx = mx; sh_inv = 1.f / sum; }
    }

    int eg = tid >> 7;
    int ct = tid & 127;
    int c4 = ct * 4;
    float4 acc = make_float4(0.f, 0.f, 0.f, 0.f);

    for (int base = r0; base < r1; base += CHUNK) {
        int cnt = min(CHUNK, r1 - base);
        __syncthreads();
        if (tid < cnt) sh_src[tid] = g_srcs[base + tid];
        __syncthreads();
        for (int t = tid; t < cnt; t += 256) {
            int s = sh_src[t];
            float ev = als[s] + aldv;
            ev = (ev > 0.f) ? ev : 0.2f * ev;
            sh_w[t] = __expf(ev - sh_mx) * sh_inv;
        }
        __syncthreads();
        int i = eg;
        for (; i + 8 <= cnt; i += 8) {
            int s0 = sh_src[i],     s1 = sh_src[i + 2],
                s2 = sh_src[i + 4], s3 = sh_src[i + 6];
            float w0 = sh_w[i],     w1 = sh_w[i + 2],
                  w2 = sh_w[i + 4], w3 = sh_w[i + 6];
            float4 v0 = *(const float4*)(h + (size_t)s0 * DIM + c4);
            float4 v1 = *(const float4*)(h + (size_t)s1 * DIM + c4);
            float4 v2 = *(const float4*)(h + (size_t)s2 * DIM + c4);
            float4 v3 = *(const float4*)(h + (size_t)s3 * DIM + c4);
            acc.x = fmaf(w0, v0.x, acc.x); acc.y = fmaf(w0, v0.y, acc.y);
            acc.z = fmaf(w0, v0.z, acc.z); acc.w = fmaf(w0, v0.w, acc.w);
            acc.x = fmaf(w1, v1.x, acc.x); acc.y = fmaf(w1, v1.y, acc.y);
            acc.z = fmaf(w1, v1.z, acc.z); acc.w = fmaf(w1, v1.w, acc.w);
            acc.x = fmaf(w2, v2.x, acc.x); acc.y = fmaf(w2, v2.y, acc.y);
            acc.z = fmaf(w2, v2.z, acc.z); acc.w = fmaf(w2, v2.w, acc.w);
            acc.x = fmaf(w3, v3.x, acc.x); acc.y = fmaf(w3, v3.y, acc.y);
            acc.z = fmaf(w3, v3.z, acc.z); acc.w = fmaf(w3, v3.w, acc.w);
        }
        for (; i < cnt; i += 2) {
            int s = sh_src[i];
            float w = sh_w[i];
            float4 v = *(const float4*)(h + (size_t)s * DIM + c4);
            acc.x = fmaf(w, v.x, acc.x); acc.y = fmaf(w, v.y, acc.y);
            acc.z = fmaf(w, v.z, acc.z); acc.w = fmaf(w, v.w, acc.w);
        }
    }

    if (eg == 1) {
        sh_part[ct][0] = acc.x; sh_part[ct][1] = acc.y;
        sh_part[ct][2] = acc.z; sh_part[ct][3] = acc.w;
    }
    __syncthreads();
    if (eg == 0) {
        acc.x += sh_part[ct][0]; acc.y += sh_part[ct][1];
        acc.z += sh_part[ct][2]; acc.w += sh_part[ct][3];
        float4 bv = *(const float4*)(bias + c4);
        acc.x += bv.x; acc.y += bv.y; acc.z += bv.z; acc.w += bv.w;
        unsigned h0, l0, h1, l1;
        split_pack2(acc.x, acc.y, h0, l0);
        split_pack2(acc.z, acc.w, h1, l1);
        int wi = dst * 256 + ct * 2;
        outH[wi] = h0; outL[wi] = l0;
        outH[wi + 1] = h1; outL[wi + 1] = l1;
    }
}

// ================= BN apply (+ optional fused final linear) ===================
__global__ __launch_bounds__(256) void bn_apply(
    const float* __restrict__ x,
    const float* __restrict__ gamma, const float* __restrict__ beta,
    unsigned* __restrict__ outH, unsigned* __restrict__ outL,
    const float* __restrict__ linw, const float* __restrict__ linb,
    float* __restrict__ out, int n, int mode,
    const float* __restrict__ sumP, const float* __restrict__ sumsqP)
{
    __shared__ float rs[8][2];
    int row = blockIdx.x;
    int c2 = threadIdx.x;
    int col = c2 * 2;
    float inv_n = 1.f / (float)n;
    float mu0 = sumP[col] * inv_n;
    float mu1 = sumP[col + 1] * inv_n;
    float var0 = sumsqP[col] * inv_n - mu0 * mu0;
    float var1 = sumsqP[col + 1] * inv_n - mu1 * mu1;
    float2 xv = *(const float2*)(x + (size_t)row * DIM + col);
    float y0 = fmaf(gamma[col] * (xv.x - mu0), rsqrtf(var0 + 1e-5f), beta[col]);
    float y1 = fmaf(gamma[col + 1] * (xv.y - mu1), rsqrtf(var1 + 1e-5f), beta[col + 1]);

    if (mode == 0) {
        unsigned hw, lw;
        split_pack2(y0, y1, hw, lw);
        int wi = row * 256 + c2;
        outH[wi] = hw; outL[wi] = lw;
    } else {
        float p0 = y0 * linw[col * 2]     + y1 * linw[col * 2 + 2];
        float p1 = y0 * linw[col * 2 + 1] + y1 * linw[col * 2 + 3];
#pragma unroll
        for (int o = 16; o; o >>= 1) {
            p0 += __shfl_down_sync(0xffffffffu, p0, o);
            p1 += __shfl_down_sync(0xffffffffu, p1, o);
        }
        int warp = c2 >> 5, lane = c2 & 31;
        if (lane == 0) { rs[warp][0] = p0; rs[warp][1] = p1; }
        __syncthreads();
        if (c2 == 0) {
            float s0 = 0.f, s1 = 0.f;
#pragma unroll
            for (int w = 0; w < 8; w++) { s0 += rs[w][0]; s1 += rs[w][1]; }
            out[row * 2 + 0] = fmaxf(s0 + linb[0], 0.f);
            out[row * 2 + 1] = fmaxf(s1 + linb[1], 0.f);
        }
    }
}

// ------------------------------------------------------------------------------
extern "C" void kernel_launch(void* const* d_in, const int* in_sizes, int n_in,
                              void* d_out, int out_size)
{
    const float* x    = (const float*)d_in[0];
    const int*   ei   = (const int*)d_in[1];
    const float* W1   = (const float*)d_in[2];
    const float* a1s  = (const float*)d_in[3];
    const float* a1d  = (const float*)d_in[4];
    const float* b1   = (const float*)d_in[5];
    const float* W2   = (const float*)d_in[6];
    const float* a2s  = (const float*)d_in[7];
    const float* a2d  = (const float*)d_in[8];
    const float* b2   = (const float*)d_in[9];
    const float* fc1w = (const float*)d_in[10];
    const float* fc1b = (const float*)d_in[11];
    const float* g1   = (const float*)d_in[12];
    const float* be1  = (const float*)d_in[13];
    const float* fc2w = (const float*)d_in[14];
    const float* fc2b = (const float*)d_in[15];
    const float* g2   = (const float*)d_in[16];
    const float* be2  = (const float*)d_in[17];
    const float* linw = (const float*)d_in[18];
    const float* linb = (const float*)d_in[19];
    float* out = (float*)d_out;

    int n = out_size / 2;        // 20000
    int E = in_sizes[1] / 2;     // 320000
    int Et = E + n;

    float *A, *C, *als, *ald, *als2, *ald2, *stats;
    unsigned *aH, *aL, *wH, *wL;
    cudaGetSymbolAddress((void**)&A,     g_bufA);
    cudaGetSymbolAddress((void**)&C,     g_bufC);
    cudaGetSymbolAddress((void**)&als,   g_als);
    cudaGetSymbolAddress((void**)&ald,   g_ald);
    cudaGetSymbolAddress((void**)&als2,  g_als2);
    cudaGetSymbolAddress((void**)&ald2,  g_ald2);
    cudaGetSymbolAddress((void**)&stats, g_stats);
    cudaGetSymbolAddress((void**)&aH,    g_actH);
    cudaGetSymbolAddress((void**)&aL,    g_actL);
    cudaGetSymbolAddress((void**)&wH,    g_WH);
    cudaGetSymbolAddress((void**)&wL,    g_WL);

    const int OW1 = 0, OF1 = 32768, OW2 = 163840, OF2 = 294912;

    // side stream + events (created once; host-side handles, no device alloc)
    static cudaStream_t s2 = nullptr;
    static cudaEvent_t evFork = nullptr, evJoin = nullptr;
    if (!s2) {
        cudaStreamCreateWithFlags(&s2, cudaStreamNonBlocking);
        cudaEventCreateWithFlags(&evFork, cudaEventDisableTiming);
        cudaEventCreateWithFlags(&evJoin, cudaEventDisableTiming);
    }

    dim3 gemm_grid(DIM / 128, (n + 127) / 128);

    // ---------------- fork: CSR build + zeroing on side stream ----------------
    cudaEventRecord(evFork, 0);
    cudaStreamWaitEvent(s2, evFork, 0);
    csr_zero<<<(n + 255) / 256, 256, 0, s2>>>(n);
    csr_hist<<<(Et + 255) / 256, 256, 0, s2>>>(ei, E, n);
    csr_scan<<<1, 1024, 0, s2>>>(n, Et);
    csr_scatter<<<(Et + 255) / 256, 256, 0, s2>>>(ei, E, n);
    zero_aux<<<(n + 255) / 256, 256, 0, s2>>>(als2, ald2, stats, n);
    cudaEventRecord(evJoin, s2);

    // ---------------- main: pack + layer-1 GEMM (independent of CSR) ----------
    pack_all<<<(106496 + n * 16 + 255) / 256, 256>>>(W1, fc1w, W2, fc2w, x,
                                                     wH, wL, aH, aL, n);
    gemm_pk<<<gemm_grid, 256>>>(aH, aL, 64, wH + OW1, wL + OW1, nullptr, A,
                                n, DIM, 64, 0, 0, 8, a1s, a1d, als, ald,
                                0, nullptr, nullptr);

    // ---------------- join, then the serial chain ----------------
    cudaStreamWaitEvent(0, evJoin, 0);
    gat_agg8<<<n, 256>>>(A, als, ald, b1, aH, aL);

    gemm_pk<<<gemm_grid, 256>>>(aH, aL, 256, wH + OF1, wL + OF1, fc1b, C,
                                n, DIM, 256, 1, 1, 0, nullptr, nullptr,
                                nullptr, nullptr, 1, stats, stats + 512);
    bn_apply<<<n, 256>>>(C, g1, be1, aH, aL, nullptr, nullptr, nullptr, n, 0,
                         stats, stats + 512);

    gemm_pk<<<gemm_grid, 256>>>(aH, aL, 256, wH + OW2, wL + OW2, nullptr, A,
                                n, DIM, 256, 0, 0, 1, a2s, a2d, als2, ald2,
                                0, nullptr, nullptr);
    gat_agg1<<<n, 256>>>(A, als2, ald2, b2, aH, aL);

    gemm_pk<<<gemm_grid, 256>>>(aH, aL, 256, wH + OF2, wL + OF2, fc2b, C,
                                n, DIM, 256, 1, 1, 0, nullptr, nullptr,
                                nullptr, nullptr, 1, stats + 1024, stats + 1536);
    bn_apply<<<n, 256>>>(C, g2, be2, nullptr, nullptr, linw, linb, out, n, 1,
                         stats + 1024, stats + 1536);
}

// round 14
// speedup vs baseline: 1.0611x; 1.0325x over previous
#include <cuda_runtime.h>
#include <cuda_bf16.h>
#include <math.h>

#define NMAX 20000
#define EMAX 320000
#define ETMAX (NMAX + EMAX)
#define DIM 512
#define H1 8
#define C1 64

// ---------------- scratch (static device memory; no allocations) -------------
__device__ float g_bufA[NMAX * DIM];   // GEMM fp32 outputs
__device__ float g_bufC[NMAX * DIM];   // fc output (post-relu) for BN
__device__ float g_als[NMAX * H1];
__device__ float g_ald[NMAX * H1];
__device__ float g_als2[NMAX];
__device__ float g_ald2[NMAX];
__device__ float g_stats[2048];        // [sum1|sumsq1|sum2|sumsq2] x 512
__device__ int g_cnt[NMAX];
__device__ int g_rowptr[NMAX + 1];
__device__ int g_cursor[NMAX];
__device__ int g_srcs[ETMAX];
// packed bf16 hi/lo operands
__device__ unsigned g_actH[NMAX * 256];
__device__ unsigned g_actL[NMAX * 256];
__device__ unsigned g_WH[425984];
__device__ unsigned g_WL[425984];

// ================= CSR build ==================================================
__global__ void csr_zero(int n) {
    int i = blockIdx.x * blockDim.x + threadIdx.x;
    if (i < n) g_cnt[i] = 0;
}

__global__ void csr_hist(const int* __restrict__ ei, int E, int n) {
    int e = blockIdx.x * blockDim.x + threadIdx.x;
    if (e >= E + n) return;
    int dst = (e < E) ? ei[E + e] : e - E;
    atomicAdd(&g_cnt[dst], 1);
}

__global__ void csr_scan(int n, int Et) {
    __shared__ int part[1024];
    int tid = threadIdx.x;
    int chunk = (n + 1023) / 1024;
    int lo = tid * chunk;
    int hi = lo + chunk; if (hi > n) hi = n; if (lo > n) lo = n;
    int s = 0;
    for (int i = lo; i < hi; i++) s += g_cnt[i];
    part[tid] = s;
    __syncthreads();
    for (int off = 1; off < 1024; off <<= 1) {
        int v = (tid >= off) ? part[tid - off] : 0;
        __syncthreads();
        part[tid] += v;
        __syncthreads();
    }
    int run = (tid == 0) ? 0 : part[tid - 1];
    for (int i = lo; i < hi; i++) {
        g_rowptr[i] = run;
        g_cursor[i] = run;
        run += g_cnt[i];
    }
    if (tid == 1023) g_rowptr[n] = Et;
}

__global__ void csr_scatter(const int* __restrict__ ei, int E, int n) {
    int e = blockIdx.x * blockDim.x + threadIdx.x;
    if (e >= E + n) return;
    int src, dst;
    if (e < E) { src = ei[e]; dst = ei[E + e]; }
    else       { src = dst = e - E; }
    int pos = atomicAdd(&g_cursor[dst], 1);
    g_srcs[pos] = src;
}

// zero layer2 attn buffers + all BN stat buffers in one launch
__global__ void zero_aux(float* __restrict__ als2, float* __restrict__ ald2,
                         float* __restrict__ stats, int n)
{
    int i = blockIdx.x * blockDim.x + threadIdx.x;
    if (i < n) { als2[i] = 0.f; ald2[i] = 0.f; }
    if (i < 2048) stats[i] = 0.f;
}

// ================= bf16 split/pack helpers ====================================
__device__ __forceinline__ void split_pack2(float v0, float v1,
                                            unsigned& hw, unsigned& lw) {
    __nv_bfloat16 h0 = __float2bfloat16_rn(v0);
    __nv_bfloat16 h1 = __float2bfloat16_rn(v1);
    __nv_bfloat16 l0 = __float2bfloat16_rn(v0 - __bfloat162float(h0));
    __nv_bfloat16 l1 = __float2bfloat16_rn(v1 - __bfloat162float(h1));
    __nv_bfloat162 hp = __halves2bfloat162(h0, h1);
    __nv_bfloat162 lp = __halves2bfloat162(l0, l1);
    hw = *(unsigned*)&hp;
    lw = *(unsigned*)&lp;
}

// one launch packs all 4 weight matrices + the input activations
__global__ void pack_all(const float* __restrict__ W1, const float* __restrict__ fc1w,
                         const float* __restrict__ W2, const float* __restrict__ fc2w,
                         const float* __restrict__ x,
                         unsigned* __restrict__ wH, unsigned* __restrict__ wL,
                         unsigned* __restrict__ aH, unsigned* __restrict__ aL, int n)
{
    int t = blockIdx.x * blockDim.x + threadIdx.x;
    if (t < 106496) {
        const float* W; int off; int u = t;
        if (t < 8192)       { W = W1;   off = 0; }
        else if (t < 40960) { W = fc1w; off = 32768;  u = t - 8192; }
        else if (t < 73728) { W = W2;   off = 163840; u = t - 40960; }
        else                { W = fc2w; off = 294912; u = t - 73728; }
        int k2 = u >> 7;
        int n4 = u & 127;
        const float* p0 = W + (size_t)(2 * k2) * DIM + n4 * 4;
        const float* p1 = p0 + DIM;
        float4 a = *(const float4*)p0;
        float4 b = *(const float4*)p1;
        uint4 h, l;
        split_pack2(a.x, b.x, h.x, l.x);
        split_pack2(a.y, b.y, h.y, l.y);
        split_pack2(a.z, b.z, h.z, l.z);
        split_pack2(a.w, b.w, h.w, l.w);
        *(uint4*)(wH + off + (size_t)u * 4) = h;
        *(uint4*)(wL + off + (size_t)u * 4) = l;
    } else {
        int u = t - 106496;
        if (u >= n * 16) return;
        const float* p = x + (size_t)u * 8;
        float4 v0 = *(const float4*)p;
        float4 v1 = *(const float4*)(p + 4);
        uint4 h, l;
        split_pack2(v0.x, v0.y, h.x, l.x);
        split_pack2(v0.z, v0.w, h.y, l.y);
        split_pack2(v1.x, v1.y, h.z, l.z);
        split_pack2(v1.z, v1.w, h.w, l.w);
        *(uint4*)(aH + (size_t)u * 4) = h;
        *(uint4*)(aL + (size_t)u * 4) = l;
    }
}

// ================= BF16x3 GEMM (2-stage cp.async) + fused epilogues ===========
__device__ __forceinline__ void mma_bf16(float* d, const unsigned* a, const unsigned* b) {
    asm volatile(
        "mma.sync.aligned.m16n8k16.row.col.f32.bf16.bf16.f32 "
        "{%0,%1,%2,%3}, {%4,%5,%6,%7}, {%8,%9}, {%0,%1,%2,%3};"
        : "+f"(d[0]), "+f"(d[1]), "+f"(d[2]), "+f"(d[3])
        : "r"(a[0]), "r"(a[1]), "r"(a[2]), "r"(a[3]), "r"(b[0]), "r"(b[1]));
}

__device__ __forceinline__ void cp16(unsigned smem_addr, const void* gptr, int src_sz) {
    asm volatile("cp.async.ca.shared.global [%0], [%1], 16, %2;"
                 :: "r"(smem_addr), "l"(gptr), "r"(src_sz));
}

#define SA 12
#define SB 136

__global__ __launch_bounds__(256, 2) void gemm_pk(
    const unsigned* __restrict__ AH, const unsigned* __restrict__ AL, int lda2,
    const unsigned* __restrict__ BH, const unsigned* __restrict__ BL,
    const float* __restrict__ bias, float* __restrict__ C,
    int M, int N, int K2, int has_bias, int do_relu,
    int attn_mode, const float* __restrict__ a_s, const float* __restrict__ a_d,
    float* __restrict__ als, float* __restrict__ ald,
    int do_stats, float* __restrict__ sumP, float* __restrict__ sumsqP)
{
    __shared__ unsigned sAH[2][128][SA];
    __shared__ unsigned sAL[2][128][SA];
    __shared__ unsigned sBH[2][8][SB];
    __shared__ unsigned sBL[2][8][SB];
    __shared__ float sm_ps[128][2], sm_pd[128][2];
    __shared__ float sm_cs[128], sm_cq[128];

    int tid  = threadIdx.x;
    int warp = tid >> 5;
    int lane = tid & 31;
    int grp  = lane >> 2;
    int l4   = lane & 3;

    int m0 = blockIdx.y * 128;
    int n0 = blockIdx.x * 128;
    int wm = (warp >> 2) * 64;
    int wn = (warp & 3) * 32;

    float acc[4][4][4];
#pragma unroll
    for (int mi = 0; mi < 4; mi++)
#pragma unroll
        for (int ni = 0; ni < 4; ni++)
#pragma unroll
            for (int r = 0; r < 4; r++) acc[mi][ni][r] = 0.f;

    int a_row = tid >> 1;
    int a_ch  = (tid & 1) * 4;
    int b_row = tid >> 5;
    int b_ch  = (tid & 31) * 4;
    int a_ok  = (m0 + a_row < M) ? 16 : 0;
    const unsigned* Arow_h = AH + (size_t)(m0 + a_row) * lda2 + a_ch;
    const unsigned* Arow_l = AL + (size_t)(m0 + a_row) * lda2 + a_ch;
    const unsigned* Brow_h = BH + (size_t)b_row * N + n0 + b_ch;
    const unsigned* Brow_l = BL + (size_t)b_row * N + n0 + b_ch;

    unsigned dAH = (unsigned)__cvta_generic_to_shared(&sAH[0][a_row][a_ch]);
    unsigned dAL = (unsigned)__cvta_generic_to_shared(&sAL[0][a_row][a_ch]);
    unsigned dBH = (unsigned)__cvta_generic_to_shared(&sBH[0][b_row][b_ch]);
    unsigned dBL = (unsigned)__cvta_generic_to_shared(&sBL[0][b_row][b_ch]);
    const unsigned stA = 128 * SA * 4;
    const unsigned stB = 8 * SB * 4;

    int nt = K2 >> 3;

    cp16(dAH, Arow_h, a_ok);
    cp16(dAL, Arow_l, a_ok);
    cp16(dBH, Brow_h, 16);
    cp16(dBL, Brow_l, 16);
    asm volatile("cp.async.commit_group;");

    int buf = 0;
    for (int t = 0; t < nt; t++) {
        if (t + 1 < nt) {
            int k2o = (t + 1) * 8;
            int nb = buf ^ 1;
            cp16(dAH + nb * stA, Arow_h + k2o, a_ok);
            cp16(dAL + nb * stA, Arow_l + k2o, a_ok);
            cp16(dBH + nb * stB, Brow_h + (size_t)k2o * N, 16);
            cp16(dBL + nb * stB, Brow_l + (size_t)k2o * N, 16);
            asm volatile("cp.async.commit_group;");
            asm volatile("cp.async.wait_group 1;");
        } else {
            asm volatile("cp.async.wait_group 0;");
        }
        __syncthreads();

        // A fragments stay resident; B fragments loaded 4 regs at a time
        unsigned ah[4][4], al[4][4];
#pragma unroll
        for (int mi = 0; mi < 4; mi++) {
            int rm = wm + mi * 16 + grp;
            ah[mi][0] = sAH[buf][rm][l4];
            ah[mi][1] = sAH[buf][rm + 8][l4];
            ah[mi][2] = sAH[buf][rm][l4 + 4];
            ah[mi][3] = sAH[buf][rm + 8][l4 + 4];
            al[mi][0] = sAL[buf][rm][l4];
            al[mi][1] = sAL[buf][rm + 8][l4];
            al[mi][2] = sAL[buf][rm][l4 + 4];
            al[mi][3] = sAL[buf][rm + 8][l4 + 4];
        }
#pragma unroll
        for (int ni = 0; ni < 4; ni++) {
            int nn = wn + ni * 8 + grp;
            unsigned bh[2], bl[2];
            bh[0] = sBH[buf][l4][nn];
            bh[1] = sBH[buf][l4 + 4][nn];
            bl[0] = sBL[buf][l4][nn];
            bl[1] = sBL[buf][l4 + 4][nn];
#pragma unroll
            for (int mi = 0; mi < 4; mi++) {
                mma_bf16(acc[mi][ni], ah[mi], bh);
                mma_bf16(acc[mi][ni], ah[mi], bl);
                mma_bf16(acc[mi][ni], al[mi], bh);
            }
        }
        __syncthreads();
        buf ^= 1;
    }

    // ---- fused epilogue ----
    int fused = (attn_mode != 0) || do_stats;
    if (fused) {
        if (tid < 128) {
            sm_ps[tid][0] = 0.f; sm_ps[tid][1] = 0.f;
            sm_pd[tid][0] = 0.f; sm_pd[tid][1] = 0.f;
            sm_cs[tid] = 0.f;    sm_cq[tid] = 0.f;
        }
        __syncthreads();
    }

    float as_c[8], ad_c[8];
    if (attn_mode) {
#pragma unroll
        for (int ni = 0; ni < 4; ni++) {
            int gc = n0 + wn + ni * 8 + l4 * 2;
            as_c[ni * 2] = a_s[gc];     as_c[ni * 2 + 1] = a_s[gc + 1];
            ad_c[ni * 2] = a_d[gc];     ad_c[ni * 2 + 1] = a_d[gc + 1];
        }
    }
    float ps[8], pd[8], cs[8], cq[8];
#pragma unroll
    for (int q = 0; q < 8; q++) { ps[q] = pd[q] = cs[q] = cq[q] = 0.f; }

#pragma unroll
    for (int mi = 0; mi < 4; mi++) {
        int r0 = m0 + wm + mi * 16 + grp;
        int r1 = r0 + 8;
        bool ok0 = (r0 < M), ok1 = (r1 < M);
#pragma unroll
        for (int ni = 0; ni < 4; ni++) {
            int c = n0 + wn + ni * 8 + l4 * 2;
            float2 v0 = make_float2(acc[mi][ni][0], acc[mi][ni][1]);
            float2 v1 = make_float2(acc[mi][ni][2], acc[mi][ni][3]);
            if (has_bias) {
                float2 bv = *(const float2*)(bias + c);
                v0.x += bv.x; v0.y += bv.y;
                v1.x += bv.x; v1.y += bv.y;
            }
            if (do_relu) {
                v0.x = fmaxf(v0.x, 0.f); v0.y = fmaxf(v0.y, 0.f);
                v1.x = fmaxf(v1.x, 0.f); v1.y = fmaxf(v1.y, 0.f);
            }
            if (attn_mode) {
                if (ok0) {
                    ps[mi * 2]     += v0.x * as_c[ni * 2] + v0.y * as_c[ni * 2 + 1];
                    pd[mi * 2]     += v0.x * ad_c[ni * 2] + v0.y * ad_c[ni * 2 + 1];
                }
                if (ok1) {
                    ps[mi * 2 + 1] += v1.x * as_c[ni * 2] + v1.y * as_c[ni * 2 + 1];
                    pd[mi * 2 + 1] += v1.x * ad_c[ni * 2] + v1.y * ad_c[ni * 2 + 1];
                }
            }
            if (do_stats) {
                float x0 = ok0 ? v0.x : 0.f, y0 = ok0 ? v0.y : 0.f;
                float x1 = ok1 ? v1.x : 0.f, y1 = ok1 ? v1.y : 0.f;
                cs[ni * 2]     += x0 + x1;
                cq[ni * 2]     += x0 * x0 + x1 * x1;
                cs[ni * 2 + 1] += y0 + y1;
                cq[ni * 2 + 1] += y0 * y0 + y1 * y1;
            }
            if (ok0) *(float2*)(C + (size_t)r0 * N + c) = v0;
            if (ok1) *(float2*)(C + (size_t)r1 * N + c) = v1;
        }
    }

    if (attn_mode) {
        int hsel = wn >> 6;
#pragma unroll
        for (int q = 0; q < 8; q++) {
            float vs = ps[q], vd = pd[q];
            vs += __shfl_xor_sync(0xffffffffu, vs, 1);
            vs += __shfl_xor_sync(0xffffffffu, vs, 2);
            vd += __shfl_xor_sync(0xffffffffu, vd, 1);
            vd += __shfl_xor_sync(0xffffffffu, vd, 2);
            if (l4 == 0) {
                int rt = wm + (q >> 1) * 16 + grp + (q & 1) * 8;
                atomicAdd(&sm_ps[rt][hsel], vs);
                atomicAdd(&sm_pd[rt][hsel], vd);
            }
        }
    }
    if (do_stats) {
#pragma unroll
        for (int q = 0; q < 8; q++) {
            float s = cs[q], sq = cq[q];
            s  += __shfl_xor_sync(0xffffffffu, s, 4);
            s  += __shfl_xor_sync(0xffffffffu, s, 8);
            s  += __shfl_xor_sync(0xffffffffu, s, 16);
            sq += __shfl_xor_sync(0xffffffffu, sq, 4);
            sq += __shfl_xor_sync(0xffffffffu, sq, 8);
            sq += __shfl_xor_sync(0xffffffffu, sq, 16);
            if (grp == 0) {
                int ct = wn + (q >> 1) * 8 + l4 * 2 + (q & 1);
                atomicAdd(&sm_cs[ct], s);
                atomicAdd(&sm_cq[ct], sq);
            }
        }
    }
    if (fused) {
        __syncthreads();
        if (tid < 128) {
            int gr = m0 + tid;
            if (attn_mode == 8 && gr < M) {
                int h0 = n0 >> 6;
                als[gr * 8 + h0]     = sm_ps[tid][0];
                als[gr * 8 + h0 + 1] = sm_ps[tid][1];
                ald[gr * 8 + h0]     = sm_pd[tid][0];
                ald[gr * 8 + h0 + 1] = sm_pd[tid][1];
            } else if (attn_mode == 1 && gr < M) {
                atomicAdd(&als[gr], sm_ps[tid][0] + sm_ps[tid][1]);
                atomicAdd(&ald[gr], sm_pd[tid][0] + sm_pd[tid][1]);
            }
            if (do_stats) {
                atomicAdd(&sumP[n0 + tid], sm_cs[tid]);
                atomicAdd(&sumsqP[n0 + tid], sm_cq[tid]);
            }
        }
    }
}

// ================= fused GAT softmax+aggregate v3 ==============================
#define CHUNK 128

__global__ __launch_bounds__(256) void gat_agg8(
    const float* __restrict__ h, const float* __restrict__ als,
    const float* __restrict__ ald, const float* __restrict__ bias,
    unsigned* __restrict__ outH, unsigned* __restrict__ outL)
{
    __shared__ int sh_src[CHUNK];
    __shared__ float sh_w[CHUNK][8];
    __shared__ float sh_mx[8], sh_inv[8], sh_ald[8];
    __shared__ float sh_part[128][4];

    int dst = blockIdx.x;
    int tid = threadIdx.x;
    int warp = tid >> 5;
    int lane = tid & 31;
    int r0 = g_rowptr[dst], r1 = g_rowptr[dst + 1];

    {
        float aldv = ald[dst * 8 + warp];
        if (lane == 0) sh_ald[warp] = aldv;
        float mx = -1e30f;
        for (int i = r0 + lane; i < r1; i += 32) {
            int s = g_srcs[i];
            float ev = als[s * 8 + warp] + aldv;
            ev = (ev > 0.f) ? ev : 0.2f * ev;
            mx = fmaxf(mx, ev);
        }
#pragma unroll
        for (int o = 16; o; o >>= 1) mx = fmaxf(mx, __shfl_xor_sync(0xffffffffu, mx, o));
        float sum = 0.f;
        for (int i = r0 + lane; i < r1; i += 32) {
            int s = g_srcs[i];
            float ev = als[s * 8 + warp] + aldv;
            ev = (ev > 0.f) ? ev : 0.2f * ev;
            sum += __expf(ev - mx);
        }
#pragma unroll
        for (int o = 16; o; o >>= 1) sum += __shfl_xor_sync(0xffffffffu, sum, o);
        if (lane == 0) { sh_mx[warp] = mx; sh_inv[warp] = 1.f / sum; }
    }

    int eg = tid >> 7;
    int ct = tid & 127;
    int c4 = ct * 4;
    int hh = ct >> 4;
    float4 acc = make_float4(0.f, 0.f, 0.f, 0.f);

    for (int base = r0; base < r1; base += CHUNK) {
        int cnt = min(CHUNK, r1 - base);
        __syncthreads();
        if (tid < cnt) sh_src[tid] = g_srcs[base + tid];
        __syncthreads();
        for (int t = tid; t < cnt * 8; t += 256) {
            int i = t >> 3, hw = t & 7;
            int s = sh_src[i];
            float ev = als[s * 8 + hw] + sh_ald[hw];
            ev = (ev > 0.f) ? ev : 0.2f * ev;
            sh_w[i][hw] = __expf(ev - sh_mx[hw]) * sh_inv[hw];
        }
        __syncthreads();
        int i = eg;
        for (; i + 8 <= cnt; i += 8) {
            int s0 = sh_src[i],     s1 = sh_src[i + 2],
                s2 = sh_src[i + 4], s3 = sh_src[i + 6];
            float w0 = sh_w[i][hh],     w1 = sh_w[i + 2][hh],
                  w2 = sh_w[i + 4][hh], w3 = sh_w[i + 6][hh];
            float4 v0 = *(const float4*)(h + (size_t)s0 * DIM + c4);
            float4 v1 = *(const float4*)(h + (size_t)s1 * DIM + c4);
            float4 v2 = *(const float4*)(h + (size_t)s2 * DIM + c4);
            float4 v3 = *(const float4*)(h + (size_t)s3 * DIM + c4);
            acc.x = fmaf(w0, v0.x, acc.x); acc.y = fmaf(w0, v0.y, acc.y);
            acc.z = fmaf(w0, v0.z, acc.z); acc.w = fmaf(w0, v0.w, acc.w);
            acc.x = fmaf(w1, v1.x, acc.x); acc.y = fmaf(w1, v1.y, acc.y);
            acc.z = fmaf(w1, v1.z, acc.z); acc.w = fmaf(w1, v1.w, acc.w);
            acc.x = fmaf(w2, v2.x, acc.x); acc.y = fmaf(w2, v2.y, acc.y);
            acc.z = fmaf(w2, v2.z, acc.z); acc.w = fmaf(w2, v2.w, acc.w);
            acc.x = fmaf(w3, v3.x, acc.x); acc.y = fmaf(w3, v3.y, acc.y);
            acc.z = fmaf(w3, v3.z, acc.z); acc.w = fmaf(w3, v3.w, acc.w);
        }
        for (; i < cnt; i += 2) {
            int s = sh_src[i];
            float w = sh_w[i][hh];
            float4 v = *(const float4*)(h + (size_t)s * DIM + c4);
            acc.x = fmaf(w, v.x, acc.x); acc.y = fmaf(w, v.y, acc.y);
            acc.z = fmaf(w, v.z, acc.z); acc.w = fmaf(w, v.w, acc.w);
        }
    }

    if (eg == 1) {
        sh_part[ct][0] = acc.x; sh_part[ct][1] = acc.y;
        sh_part[ct][2] = acc.z; sh_part[ct][3] = acc.w;
    }
    __syncthreads();
    if (eg == 0) {
        acc.x += sh_part[ct][0]; acc.y += sh_part[ct][1];
        acc.z += sh_part[ct][2]; acc.w += sh_part[ct][3];
        float4 bv = *(const float4*)(bias + c4);
        acc.x += bv.x; acc.y += bv.y; acc.z += bv.z; acc.w += bv.w;
        unsigned h0, l0, h1, l1;
        split_pack2(acc.x, acc.y, h0, l0);
        split_pack2(acc.z, acc.w, h1, l1);
        int wi = dst * 256 + ct * 2;
        outH[wi] = h0; outL[wi] = l0;
        outH[wi + 1] = h1; outL[wi + 1] = l1;
    }
}

__global__ __launch_bounds__(256) void gat_agg1(
    const float* __restrict__ h, const float* __restrict__ als,
    const float* __restrict__ ald, const float* __restrict__ bias,
    unsigned* __restrict__ outH, unsigned* __restrict__ outL)
{
    __shared__ int sh_src[CHUNK];
    __shared__ float sh_w[CHUNK];
    __shared__ float sh_mx, sh_inv;
    __shared__ float sh_part[128][4];

    int dst = blockIdx.x;
    int tid = threadIdx.x;
    int r0 = g_rowptr[dst], r1 = g_rowptr[dst + 1];
    float aldv = ald[dst];

    if (tid < 32) {
        float mx = -1e30f;
        for (int i = r0 + tid; i < r1; i += 32) {
            int s = g_srcs[i];
            float ev = als[s] + aldv;
            ev = (ev > 0.f) ? ev : 0.2f * ev;
            mx = fmaxf(mx, ev);
        }
#pragma unroll
        for (int o = 16; o; o >>= 1) mx = fmaxf(mx, __shfl_xor_sync(0xffffffffu, mx, o));
        float sum = 0.f;
        for (int i = r0 + tid; i < r1; i += 32) {
            int s = g_srcs[i];
            float ev = als[s] + aldv;
            ev = (ev > 0.f) ? ev : 0.2f * ev;
            sum += __expf(ev - mx);
        }
#pragma unroll
        for (int o = 16; o; o >>= 1) sum += __shfl_xor_sync(0xffffffffu, sum, o);
        if (tid == 0) { sh_mx = mx; sh_inv = 1.f / sum; }
    }

    int eg = tid >> 7;
    int ct = tid & 127;
    int c4 = ct * 4;
    float4 acc = make_float4(0.f, 0.f, 0.f, 0.f);

    for (int base = r0; base < r1; base += CHUNK) {
        int cnt = min(CHUNK, r1 - base);
        __syncthreads();
        if (tid < cnt) sh_src[tid] = g_srcs[base + tid];
        __syncthreads();
        for (int t = tid; t < cnt; t += 256) {
            int s = sh_src[t];
            float ev = als[s] + aldv;
            ev = (ev > 0.f) ? ev : 0.2f * ev;
            sh_w[t] = __expf(ev - sh_mx) * sh_inv;
        }
        __syncthreads();
        int i = eg;
        for (; i + 8 <= cnt; i += 8) {
            int s0 = sh_src[i],     s1 = sh_src[i + 2],
                s2 = sh_src[i + 4], s3 = sh_src[i + 6];
            float w0 = sh_w[i],     w1 = sh_w[i + 2],
                  w2 = sh_w[i + 4], w3 = sh_w[i + 6];
            float4 v0 = *(const float4*)(h + (size_t)s0 * DIM + c4);
            float4 v1 = *(const float4*)(h + (size_t)s1 * DIM + c4);
            float4 v2 = *(const float4*)(h + (size_t)s2 * DIM + c4);
            float4 v3 = *(const float4*)(h + (size_t)s3 * DIM + c4);
            acc.x = fmaf(w0, v0.x, acc.x); acc.y = fmaf(w0, v0.y, acc.y);
            acc.z = fmaf(w0, v0.z, acc.z); acc.w = fmaf(w0, v0.w, acc.w);
            acc.x = fmaf(w1, v1.x, acc.x); acc.y = fmaf(w1, v1.y, acc.y);
            acc.z = fmaf(w1, v1.z, acc.z); acc.w = fmaf(w1, v1.w, acc.w);
            acc.x = fmaf(w2, v2.x, acc.x); acc.y = fmaf(w2, v2.y, acc.y);
            acc.z = fmaf(w2, v2.z, acc.z); acc.w = fmaf(w2, v2.w, acc.w);
            acc.x = fmaf(w3, v3.x, acc.x); acc.y = fmaf(w3, v3.y, acc.y);
            acc.z = fmaf(w3, v3.z, acc.z); acc.w = fmaf(w3, v3.w, acc.w);
        }
        for (; i < cnt; i += 2) {
            int s = sh_src[i];
            float w = sh_w[i];
            float4 v = *(const float4*)(h + (size_t)s * DIM + c4);
            acc.x = fmaf(w, v.x, acc.x); acc.y = fmaf(w, v.y, acc.y);
            acc.z = fmaf(w, v.z, acc.z); acc.w = fmaf(w, v.w, acc.w);
        }
    }

    if (eg == 1) {
        sh_part[ct][0] = acc.x; sh_part[ct][1] = acc.y;
        sh_part[ct][2] = acc.z; sh_part[ct][3] = acc.w;
    }
    __syncthreads();
    if (eg == 0) {
        acc.x += sh_part[ct][0]; acc.y += sh_part[ct][1];
        acc.z += sh_part[ct][2]; acc.w += sh_part[ct][3];
        float4 bv = *(const float4*)(bias + c4);
        acc.x += bv.x; acc.y += bv.y; acc.z += bv.z; acc.w += bv.w;
        unsigned h0, l0, h1, l1;
        split_pack2(acc.x, acc.y, h0, l0);
        split_pack2(acc.z, acc.w, h1, l1);
        int wi = dst * 256 + ct * 2;
        outH[wi] = h0; outL[wi] = l0;
        outH[wi + 1] = h1; outL[wi + 1] = l1;
    }
}

// ================= BN apply (+ optional fused final linear) ===================
__global__ __launch_bounds__(256) void bn_apply(
    const float* __restrict__ x,
    const float* __restrict__ gamma, const float* __restrict__ beta,
    unsigned* __restrict__ outH, unsigned* __restrict__ outL,
    const float* __restrict__ linw, const float* __restrict__ linb,
    float* __restrict__ out, int n, int mode,
    const float* __restrict__ sumP, const float* __restrict__ sumsqP)
{
    __shared__ float rs[8][2];
    int row = blockIdx.x;
    int c2 = threadIdx.x;
    int col = c2 * 2;
    float inv_n = 1.f / (float)n;
    float mu0 = sumP[col] * inv_n;
    float mu1 = sumP[col + 1] * inv_n;
    float var0 = sumsqP[col] * inv_n - mu0 * mu0;
    float var1 = sumsqP[col + 1] * inv_n - mu1 * mu1;
    float2 xv = *(const float2*)(x + (size_t)row * DIM + col);
    float y0 = fmaf(gamma[col] * (xv.x - mu0), rsqrtf(var0 + 1e-5f), beta[col]);
    float y1 = fmaf(gamma[col + 1] * (xv.y - mu1), rsqrtf(var1 + 1e-5f), beta[col + 1]);

    if (mode == 0) {
        unsigned hw, lw;
        split_pack2(y0, y1, hw, lw);
        int wi = row * 256 + c2;
        outH[wi] = hw; outL[wi] = lw;
    } else {
        float p0 = y0 * linw[col * 2]     + y1 * linw[col * 2 + 2];
        float p1 = y0 * linw[col * 2 + 1] + y1 * linw[col * 2 + 3];
#pragma unroll
        for (int o = 16; o; o >>= 1) {
            p0 += __shfl_down_sync(0xffffffffu, p0, o);
            p1 += __shfl_down_sync(0xffffffffu, p1, o);
        }
        int warp = c2 >> 5, lane = c2 & 31;
        if (lane == 0) { rs[warp][0] = p0; rs[warp][1] = p1; }
        __syncthreads();
        if (c2 == 0) {
            float s0 = 0.f, s1 = 0.f;
#pragma unroll
            for (int w = 0; w < 8; w++) { s0 += rs[w][0]; s1 += rs[w][1]; }
            out[row * 2 + 0] = fmaxf(s0 + linb[0], 0.f);
            out[row * 2 + 1] = fmaxf(s1 + linb[1], 0.f);
        }
    }
}

// ------------------------------------------------------------------------------
extern "C" void kernel_launch(void* const* d_in, const int* in_sizes, int n_in,
                              void* d_out, int out_size)
{
    const float* x    = (const float*)d_in[0];
    const int*   ei   = (const int*)d_in[1];
    const float* W1   = (const float*)d_in[2];
    const float* a1s  = (const float*)d_in[3];
    const float* a1d  = (const float*)d_in[4];
    const float* b1   = (const float*)d_in[5];
    const float* W2   = (const float*)d_in[6];
    const float* a2s  = (const float*)d_in[7];
    const float* a2d  = (const float*)d_in[8];
    const float* b2   = (const float*)d_in[9];
    const float* fc1w = (const float*)d_in[10];
    const float* fc1b = (const float*)d_in[11];
    const float* g1   = (const float*)d_in[12];
    const float* be1  = (const float*)d_in[13];
    const float* fc2w = (const float*)d_in[14];
    const float* fc2b = (const float*)d_in[15];
    const float* g2   = (const float*)d_in[16];
    const float* be2  = (const float*)d_in[17];
    const float* linw = (const float*)d_in[18];
    const float* linb = (const float*)d_in[19];
    float* out = (float*)d_out;

    int n = out_size / 2;        // 20000
    int E = in_sizes[1] / 2;     // 320000
    int Et = E + n;

    float *A, *C, *als, *ald, *als2, *ald2, *stats;
    unsigned *aH, *aL, *wH, *wL;
    cudaGetSymbolAddress((void**)&A,     g_bufA);
    cudaGetSymbolAddress((void**)&C,     g_bufC);
    cudaGetSymbolAddress((void**)&als,   g_als);
    cudaGetSymbolAddress((void**)&ald,   g_ald);
    cudaGetSymbolAddress((void**)&als2,  g_als2);
    cudaGetSymbolAddress((void**)&ald2,  g_ald2);
    cudaGetSymbolAddress((void**)&stats, g_stats);
    cudaGetSymbolAddress((void**)&aH,    g_actH);
    cudaGetSymbolAddress((void**)&aL,    g_actL);
    cudaGetSymbolAddress((void**)&wH,    g_WH);
    cudaGetSymbolAddress((void**)&wL,    g_WL);

    const int OW1 = 0, OF1 = 32768, OW2 = 163840, OF2 = 294912;

    static cudaStream_t s2 = nullptr;
    static cudaEvent_t evFork = nullptr, evJoin = nullptr;
    if (!s2) {
        cudaStreamCreateWithFlags(&s2, cudaStreamNonBlocking);
        cudaEventCreateWithFlags(&evFork, cudaEventDisableTiming);
        cudaEventCreateWithFlags(&evJoin, cudaEventDisableTiming);
    }

    dim3 gemm_grid(DIM / 128, (n + 127) / 128);

    // ---------------- fork: CSR build + zeroing on side stream ----------------
    cudaEventRecord(evFork, 0);
    cudaStreamWaitEvent(s2, evFork, 0);
    csr_zero<<<(n + 255) / 256, 256, 0, s2>>>(n);
    csr_hist<<<(Et + 255) / 256, 256, 0, s2>>>(ei, E, n);
    csr_scan<<<1, 1024, 0, s2>>>(n, Et);
    csr_scatter<<<(Et + 255) / 256, 256, 0, s2>>>(ei, E, n);
    zero_aux<<<(n + 255) / 256, 256, 0, s2>>>(als2, ald2, stats, n);
    cudaEventRecord(evJoin, s2);

    // ---------------- main: pack + layer-1 GEMM (independent of CSR) ----------
    pack_all<<<(106496 + n * 16 + 255) / 256, 256>>>(W1, fc1w, W2, fc2w, x,
                                                     wH, wL, aH, aL, n);
    gemm_pk<<<gemm_grid, 256>>>(aH, aL, 64, wH + OW1, wL + OW1, nullptr, A,
                                n, DIM, 64, 0, 0, 8, a1s, a1d, als, ald,
                                0, nullptr, nullptr);

    // ---------------- join, then the serial chain ----------------
    cudaStreamWaitEvent(0, evJoin, 0);
    gat_agg8<<<n, 256>>>(A, als, ald, b1, aH, aL);

    gemm_pk<<<gemm_grid, 256>>>(aH, aL, 256, wH + OF1, wL + OF1, fc1b, C,
                                n, DIM, 256, 1, 1, 0, nullptr, nullptr,
                                nullptr, nullptr, 1, stats, stats + 512);
    bn_apply<<<n, 256>>>(C, g1, be1, aH, aL, nullptr, nullptr, nullptr, n, 0,
                         stats, stats + 512);

    gemm_pk<<<gemm_grid, 256>>>(aH, aL, 256, wH + OW2, wL + OW2, nullptr, A,
                                n, DIM, 256, 0, 0, 1, a2s, a2d, als2, ald2,
                                0, nullptr, nullptr);
    gat_agg1<<<n, 256>>>(A, als2, ald2, b2, aH, aL);

    gemm_pk<<<gemm_grid, 256>>>(aH, aL, 256, wH + OF2, wL + OF2, fc2b, C,
                                n, DIM, 256, 1, 1, 0, nullptr, nullptr,
                                nullptr, nullptr, 1, stats + 1024, stats + 1536);
    bn_apply<<<n, 256>>>(C, g2, be2, nullptr, nullptr, linw, linb, out, n, 1,
                         stats + 1024, stats + 1536);
}